// round 2
// baseline (speedup 1.0000x reference)
#include <cuda_runtime.h>
#include <cstdint>

#define T_SEQ   2048
#define NH      16
#define HD      64
#define C_EMB   1024
#define BATCH   4
#define M_ROWS  (BATCH * T_SEQ)   // 8192

// Scratch (allocation-free rule: __device__ globals)
__device__ float g_Q[(size_t)M_ROWS * C_EMB];
__device__ float g_K[(size_t)M_ROWS * C_EMB];
__device__ float g_V[(size_t)M_ROWS * C_EMB];
__device__ float g_Yatt[(size_t)M_ROWS * C_EMB];

// ---------------------------------------------------------------------------
// SGEMM: C = A[M,K] @ B[K,N] + bias, 128x128 tile, BK=8, 256 thr, 8x8/thread
// MODE 0: row-major output [M,N]
// MODE 1: QKV layout: row=(b,t), col=(h,d) -> out[((b*NH+h)*T + t)*HD + d]
// ---------------------------------------------------------------------------
template <int MODE>
__global__ __launch_bounds__(256) void sgemm_bias(
    const float* __restrict__ A, const float* __restrict__ B,
    const float* __restrict__ bias, float* __restrict__ Cout,
    int M, int N, int K)
{
    __shared__ float As[8][128];   // transposed: As[k][m]
    __shared__ float Bs[8][128];   // Bs[k][n]

    const int tid = threadIdx.x;
    const int bm = blockIdx.y * 128;
    const int bn = blockIdx.x * 128;
    const int tx = tid & 15;
    const int ty = tid >> 4;

    const int arow = tid >> 1;
    const int acol = (tid & 1) << 2;
    const int brow = tid >> 5;
    const int bcol = (tid & 31) << 2;

    const float* Aptr = A + (size_t)(bm + arow) * K + acol;
    const float* Bptr = B + (size_t)brow * N + bn + bcol;

    float4 a4 = *(const float4*)Aptr;
    float4 b4 = *(const float4*)Bptr;

    float acc[8][8];
#pragma unroll
    for (int i = 0; i < 8; i++)
#pragma unroll
        for (int j = 0; j < 8; j++) acc[i][j] = 0.f;

    for (int k0 = 0; k0 < K; k0 += 8) {
        As[acol + 0][arow] = a4.x;
        As[acol + 1][arow] = a4.y;
        As[acol + 2][arow] = a4.z;
        As[acol + 3][arow] = a4.w;
        *(float4*)&Bs[brow][bcol] = b4;
        __syncthreads();

        float4 a4n = a4, b4n = b4;
        if (k0 + 8 < K) {
            Aptr += 8;
            Bptr += (size_t)8 * N;
            a4n = *(const float4*)Aptr;
            b4n = *(const float4*)Bptr;
        }

#pragma unroll
        for (int kk = 0; kk < 8; kk++) {
            float a[8], b[8];
            *(float4*)&a[0] = *(const float4*)&As[kk][ty * 8];
            *(float4*)&a[4] = *(const float4*)&As[kk][ty * 8 + 4];
            *(float4*)&b[0] = *(const float4*)&Bs[kk][tx * 8];
            *(float4*)&b[4] = *(const float4*)&Bs[kk][tx * 8 + 4];
#pragma unroll
            for (int i = 0; i < 8; i++)
#pragma unroll
                for (int j = 0; j < 8; j++) acc[i][j] += a[i] * b[j];
        }
        __syncthreads();
        a4 = a4n;
        b4 = b4n;
    }

    // bias for this thread's 8 output columns, loaded once
    float bv8[8];
#pragma unroll
    for (int j = 0; j < 8; j++) bv8[j] = bias[bn + tx * 8 + j];

#pragma unroll
    for (int i = 0; i < 8; i++) {
        const int row = bm + ty * 8 + i;
#pragma unroll
        for (int j = 0; j < 8; j++) {
            const int col = bn + tx * 8 + j;
            const float v = acc[i][j] + bv8[j];
            if (MODE == 0) {
                Cout[(size_t)row * N + col] = v;
            } else {
                const int b_ = row >> 11;          // row / T_SEQ
                const int t_ = row & (T_SEQ - 1);
                const int h_ = col >> 6;           // col / HD
                const int d_ = col & (HD - 1);
                Cout[(((size_t)b_ * NH + h_) * T_SEQ + t_) * HD + d_] = v;
            }
        }
    }
}

// ---------------------------------------------------------------------------
// Flash attention (fp32, causal). Block = 64 queries x full D=64.
// 256 threads as 16x16, 4x4 micro-tiles. Online softmax.
// smem: Qts/Kts transposed (d-major) [64][68], Vs natural [64][68], Ps [64][68]
// ---------------------------------------------------------------------------
#define APAD 68
#define ATTN_SMEM (4 * 64 * APAD * (int)sizeof(float))  // 69632 B

__global__ __launch_bounds__(256) void attn_kernel(
    const float* __restrict__ Q, const float* __restrict__ K,
    const float* __restrict__ V, float* __restrict__ Y)
{
    extern __shared__ float sm[];
    float* Qts = sm;                  // [d][row]
    float* Kts = sm + 64 * APAD;      // [d][key]
    float* Vs  = sm + 2 * 64 * APAD;  // [key][d]
    float* Ps  = sm + 3 * 64 * APAD;  // [row][key]

    const int tid = threadIdx.x;
    const int tx = tid & 15;
    const int ty = tid >> 4;
    const int bh = blockIdx.y;
    const int qb = blockIdx.x;
    const int q0 = qb * 64;

    const float* Qg = Q + ((size_t)bh * T_SEQ + q0) * HD;
    const float* Kg = K + (size_t)bh * T_SEQ * HD;
    const float* Vg = V + (size_t)bh * T_SEQ * HD;

    // Load + transpose Q tile (once)
#pragma unroll
    for (int r = 0; r < 4; r++) {
        const int idx = tid + r * 256;          // [0,1024)
        const int row = idx >> 4;
        const int d4  = (idx & 15) << 2;
        const float4 v = *(const float4*)(Qg + row * HD + d4);
        Qts[(d4 + 0) * APAD + row] = v.x;
        Qts[(d4 + 1) * APAD + row] = v.y;
        Qts[(d4 + 2) * APAD + row] = v.z;
        Qts[(d4 + 3) * APAD + row] = v.w;
    }

    float o[4][4];
    float m_i[4], l_i[4];
#pragma unroll
    for (int i = 0; i < 4; i++) {
        m_i[i] = -1e30f;
        l_i[i] = 0.f;
#pragma unroll
        for (int d = 0; d < 4; d++) o[i][d] = 0.f;
    }

    for (int j = 0; j <= qb; j++) {
        __syncthreads();  // protect Kts/Vs/Ps from previous iteration's readers
        const float* Kj = Kg + (size_t)j * 64 * HD;
        const float* Vj = Vg + (size_t)j * 64 * HD;
#pragma unroll
        for (int r = 0; r < 4; r++) {
            const int idx = tid + r * 256;
            const int row = idx >> 4;
            const int d4  = (idx & 15) << 2;
            const float4 kv = *(const float4*)(Kj + row * HD + d4);
            Kts[(d4 + 0) * APAD + row] = kv.x;
            Kts[(d4 + 1) * APAD + row] = kv.y;
            Kts[(d4 + 2) * APAD + row] = kv.z;
            Kts[(d4 + 3) * APAD + row] = kv.w;
            const float4 vv = *(const float4*)(Vj + row * HD + d4);
            *(float4*)&Vs[row * APAD + d4] = vv;
        }
        __syncthreads();

        // S = Q @ K^T  (4x4 per thread)
        float s[4][4];
#pragma unroll
        for (int i = 0; i < 4; i++)
#pragma unroll
            for (int jj = 0; jj < 4; jj++) s[i][jj] = 0.f;

#pragma unroll 8
        for (int kk = 0; kk < 64; kk++) {
            const float a0 = Qts[kk * APAD + ty * 4 + 0];
            const float a1 = Qts[kk * APAD + ty * 4 + 1];
            const float a2 = Qts[kk * APAD + ty * 4 + 2];
            const float a3 = Qts[kk * APAD + ty * 4 + 3];
            const float4 bb = *(const float4*)&Kts[kk * APAD + tx * 4];
            s[0][0] += a0 * bb.x; s[0][1] += a0 * bb.y; s[0][2] += a0 * bb.z; s[0][3] += a0 * bb.w;
            s[1][0] += a1 * bb.x; s[1][1] += a1 * bb.y; s[1][2] += a1 * bb.z; s[1][3] += a1 * bb.w;
            s[2][0] += a2 * bb.x; s[2][1] += a2 * bb.y; s[2][2] += a2 * bb.z; s[2][3] += a2 * bb.w;
            s[3][0] += a3 * bb.x; s[3][1] += a3 * bb.y; s[3][2] += a3 * bb.z; s[3][3] += a3 * bb.w;
        }

        // scale; causal mask only on the diagonal block
#pragma unroll
        for (int i = 0; i < 4; i++)
#pragma unroll
            for (int jj = 0; jj < 4; jj++) s[i][jj] *= 0.125f;  // 1/sqrt(64)
        if (j == qb) {
#pragma unroll
            for (int i = 0; i < 4; i++)
#pragma unroll
                for (int jj = 0; jj < 4; jj++)
                    if (tx * 4 + jj > ty * 4 + i) s[i][jj] = -1e30f;
        }

        // online softmax update (reduce across the 16-lane row group)
#pragma unroll
        for (int i = 0; i < 4; i++) {
            float mv = fmaxf(fmaxf(s[i][0], s[i][1]), fmaxf(s[i][2], s[i][3]));
            mv = fmaxf(mv, __shfl_xor_sync(0xffffffffu, mv, 1));
            mv = fmaxf(mv, __shfl_xor_sync(0xffffffffu, mv, 2));
            mv = fmaxf(mv, __shfl_xor_sync(0xffffffffu, mv, 4));
            mv = fmaxf(mv, __shfl_xor_sync(0xffffffffu, mv, 8));
            const float mn = fmaxf(m_i[i], mv);
            const float alpha = __expf(m_i[i] - mn);
            m_i[i] = mn;
            float rs = 0.f;
#pragma unroll
            for (int jj = 0; jj < 4; jj++) {
                const float p = __expf(s[i][jj] - mn);
                Ps[(ty * 4 + i) * APAD + tx * 4 + jj] = p;
                rs += p;
            }
            rs += __shfl_xor_sync(0xffffffffu, rs, 1);
            rs += __shfl_xor_sync(0xffffffffu, rs, 2);
            rs += __shfl_xor_sync(0xffffffffu, rs, 4);
            rs += __shfl_xor_sync(0xffffffffu, rs, 8);
            l_i[i] = l_i[i] * alpha + rs;
#pragma unroll
            for (int d = 0; d < 4; d++) o[i][d] *= alpha;
        }
        __syncthreads();  // Ps visible to all

        // O += P @ V
#pragma unroll 8
        for (int c = 0; c < 64; c++) {
            const float4 bb = *(const float4*)&Vs[c * APAD + tx * 4];
            const float a0 = Ps[(ty * 4 + 0) * APAD + c];
            const float a1 = Ps[(ty * 4 + 1) * APAD + c];
            const float a2 = Ps[(ty * 4 + 2) * APAD + c];
            const float a3 = Ps[(ty * 4 + 3) * APAD + c];
            o[0][0] += a0 * bb.x; o[0][1] += a0 * bb.y; o[0][2] += a0 * bb.z; o[0][3] += a0 * bb.w;
            o[1][0] += a1 * bb.x; o[1][1] += a1 * bb.y; o[1][2] += a1 * bb.z; o[1][3] += a1 * bb.w;
            o[2][0] += a2 * bb.x; o[2][1] += a2 * bb.y; o[2][2] += a2 * bb.z; o[2][3] += a2 * bb.w;
            o[3][0] += a3 * bb.x; o[3][1] += a3 * bb.y; o[3][2] += a3 * bb.z; o[3][3] += a3 * bb.w;
        }
    }

    // write back to [B,T,C] with C = (h,d)
    const int b_ = bh >> 4;
    const int h_ = bh & 15;
#pragma unroll
    for (int i = 0; i < 4; i++) {
        const int t_ = q0 + ty * 4 + i;
        const float inv = 1.0f / l_i[i];
        const float4 vo = make_float4(o[i][0] * inv, o[i][1] * inv,
                                      o[i][2] * inv, o[i][3] * inv);
        *(float4*)&Y[((size_t)b_ * T_SEQ + t_) * C_EMB + h_ * HD + tx * 4] = vo;
    }
}

// ---------------------------------------------------------------------------
extern "C" void kernel_launch(void* const* d_in, const int* in_sizes, int n_in,
                              void* d_out, int out_size)
{
    const float* x  = (const float*)d_in[0];
    const float* Wq = (const float*)d_in[1];
    const float* bq = (const float*)d_in[2];
    const float* Wk = (const float*)d_in[3];
    const float* bk = (const float*)d_in[4];
    const float* Wv = (const float*)d_in[5];
    const float* bv = (const float*)d_in[6];
    const float* Wp = (const float*)d_in[7];
    const float* bp = (const float*)d_in[8];
    float* out = (float*)d_out;

    float *Qp, *Kp, *Vp, *Yp;
    cudaGetSymbolAddress((void**)&Qp, g_Q);
    cudaGetSymbolAddress((void**)&Kp, g_K);
    cudaGetSymbolAddress((void**)&Vp, g_V);
    cudaGetSymbolAddress((void**)&Yp, g_Yatt);

    cudaFuncSetAttribute(attn_kernel,
                         cudaFuncAttributeMaxDynamicSharedMemorySize, ATTN_SMEM);

    const dim3 gg(C_EMB / 128, M_ROWS / 128);  // (8, 64)
    sgemm_bias<1><<<gg, 256>>>(x, Wq, bq, Qp, M_ROWS, C_EMB, C_EMB);
    sgemm_bias<1><<<gg, 256>>>(x, Wk, bk, Kp, M_ROWS, C_EMB, C_EMB);
    sgemm_bias<1><<<gg, 256>>>(x, Wv, bv, Vp, M_ROWS, C_EMB, C_EMB);

    attn_kernel<<<dim3(T_SEQ / 64, BATCH * NH), 256, ATTN_SMEM>>>(Qp, Kp, Vp, Yp);

    sgemm_bias<0><<<gg, 256>>>(Yp, Wp, bp, out, M_ROWS, C_EMB, C_EMB);
}

// round 3
// speedup vs baseline: 1.7354x; 1.7354x over previous
#include <cuda_runtime.h>
#include <cstdint>

#define T_SEQ   2048
#define NH      16
#define HD      64
#define C_EMB   1024
#define BATCH   4
#define M_ROWS  (BATCH * T_SEQ)   // 8192

// Scratch (allocation-free rule: __device__ globals)
__device__ float g_Q[(size_t)M_ROWS * C_EMB];
__device__ float g_K[(size_t)M_ROWS * C_EMB];
__device__ float g_V[(size_t)M_ROWS * C_EMB];
__device__ float g_Yatt[(size_t)M_ROWS * C_EMB];

// ---------------------------------------------------------------------------
// tf32 tensor-core GEMM: C = A[M,K] @ B[K,N] + bias
// 128x128x16 block tile, 256 threads (8 warps), warp tile 64x32,
// mma.sync.aligned.m16n8k8.row.col.f32.tf32.tf32.f32
// smem k-major with +8 pad (stride 136) -> conflict-free fragment loads.
// tf32 conversion happens once on the global->smem path.
// MODE 0: row-major output [M,N]
// MODE 1: QKV layout: row=(b,t), col=(h,d) -> out[((b*NH+h)*T + t)*HD + d]
// ---------------------------------------------------------------------------
#define BM 128
#define BN 128
#define BK 16
#define LDST 136   // BM + 8 pad

__device__ __forceinline__ uint32_t f2tf32(float x) {
    uint32_t r;
    asm("cvt.rna.tf32.f32 %0, %1;" : "=r"(r) : "f"(x));
    return r;
}

__device__ __forceinline__ void mma_tf32(float* c, const uint32_t* a, const uint32_t* b) {
    asm volatile(
        "mma.sync.aligned.m16n8k8.row.col.f32.tf32.tf32.f32 "
        "{%0,%1,%2,%3}, {%4,%5,%6,%7}, {%8,%9}, {%0,%1,%2,%3};"
        : "+f"(c[0]), "+f"(c[1]), "+f"(c[2]), "+f"(c[3])
        : "r"(a[0]), "r"(a[1]), "r"(a[2]), "r"(a[3]), "r"(b[0]), "r"(b[1]));
}

template <int MODE>
__global__ __launch_bounds__(256) void gemm_tf32_bias(
    const float* __restrict__ A, const float* __restrict__ B,
    const float* __restrict__ bias, float* __restrict__ Cout,
    int M, int N, int K)
{
    __shared__ uint32_t As[BK][LDST];   // As[k][m], tf32 bits
    __shared__ uint32_t Bs[BK][LDST];   // Bs[k][n], tf32 bits

    const int tid  = threadIdx.x;
    const int bm   = blockIdx.y * BM;
    const int bn   = blockIdx.x * BN;
    const int wid  = tid >> 5;
    const int lane = tid & 31;
    const int g    = lane >> 2;      // group id (0..7)
    const int tig  = lane & 3;       // thread in group (0..3)
    const int wm   = (wid & 1) * 64; // warp row base in tile
    const int wn   = (wid >> 1) * 32;// warp col base in tile

    // A loads: 512 float4 chunks (128 m x 16 k), 2 per thread
    const int am0 = tid >> 1;               // idx0 = tid  -> m in [0,128)
    const int ak0 = (tid & 1) << 3;         // hmm: 2 chunks of k? recompute below
    // chunk mapping: idx in [0,512): m = idx>>2, kq = (idx&3)*4
    const int a_m0 = tid >> 2;              const int a_k0 = (tid & 3) << 2;
    const int a_m1 = (tid + 256) >> 2;      const int a_k1 = ((tid + 256) & 3) << 2;
    (void)am0; (void)ak0;
    // B loads: 512 float4 chunks (16 k x 32 n4), 2 per thread
    const int b_k0 = tid >> 5;              const int b_n0 = (tid & 31) << 2;
    const int b_k1 = (tid + 256) >> 5;      const int b_n1 = ((tid + 256) & 31) << 2;

    const float* Ap0 = A + (size_t)(bm + a_m0) * K + a_k0;
    const float* Ap1 = A + (size_t)(bm + a_m1) * K + a_k1;
    const float* Bp0 = B + (size_t)b_k0 * N + bn + b_n0;
    const float* Bp1 = B + (size_t)b_k1 * N + bn + b_n1;

    float4 av0 = *(const float4*)Ap0;
    float4 av1 = *(const float4*)Ap1;
    float4 bv0 = *(const float4*)Bp0;
    float4 bv1 = *(const float4*)Bp1;

    float acc[4][4][4];
#pragma unroll
    for (int i = 0; i < 4; i++)
#pragma unroll
        for (int j = 0; j < 4; j++)
#pragma unroll
            for (int r = 0; r < 4; r++) acc[i][j][r] = 0.f;

    for (int k0 = 0; k0 < K; k0 += BK) {
        // store (with tf32 convert)
        As[a_k0 + 0][a_m0] = f2tf32(av0.x);
        As[a_k0 + 1][a_m0] = f2tf32(av0.y);
        As[a_k0 + 2][a_m0] = f2tf32(av0.z);
        As[a_k0 + 3][a_m0] = f2tf32(av0.w);
        As[a_k1 + 0][a_m1] = f2tf32(av1.x);
        As[a_k1 + 1][a_m1] = f2tf32(av1.y);
        As[a_k1 + 2][a_m1] = f2tf32(av1.z);
        As[a_k1 + 3][a_m1] = f2tf32(av1.w);
        {
            uint4 t0 = make_uint4(f2tf32(bv0.x), f2tf32(bv0.y), f2tf32(bv0.z), f2tf32(bv0.w));
            uint4 t1 = make_uint4(f2tf32(bv1.x), f2tf32(bv1.y), f2tf32(bv1.z), f2tf32(bv1.w));
            *(uint4*)&Bs[b_k0][b_n0] = t0;
            *(uint4*)&Bs[b_k1][b_n1] = t1;
        }
        __syncthreads();

        if (k0 + BK < K) {
            Ap0 += BK; Ap1 += BK;
            Bp0 += (size_t)BK * N; Bp1 += (size_t)BK * N;
            av0 = *(const float4*)Ap0;
            av1 = *(const float4*)Ap1;
            bv0 = *(const float4*)Bp0;
            bv1 = *(const float4*)Bp1;
        }

#pragma unroll
        for (int ks = 0; ks < BK; ks += 8) {
            uint32_t af[4][4], bf[4][2];
#pragma unroll
            for (int i = 0; i < 4; i++) {
                const int mb = wm + 16 * i;
                af[i][0] = As[ks + tig][mb + g];
                af[i][1] = As[ks + tig][mb + g + 8];
                af[i][2] = As[ks + tig + 4][mb + g];
                af[i][3] = As[ks + tig + 4][mb + g + 8];
            }
#pragma unroll
            for (int j = 0; j < 4; j++) {
                const int nb = wn + 8 * j;
                bf[j][0] = Bs[ks + tig][nb + g];
                bf[j][1] = Bs[ks + tig + 4][nb + g];
            }
#pragma unroll
            for (int i = 0; i < 4; i++)
#pragma unroll
                for (int j = 0; j < 4; j++)
                    mma_tf32(acc[i][j], af[i], bf[j]);
        }
        __syncthreads();
    }

    // Epilogue: thread owns (row0, col0),(row0,col0+1),(row0+8,col0),(row0+8,col0+1)
    // per (i,j) tile; row0 = bm+wm+16i+g, col0 = bn+wn+8j+2*tig
#pragma unroll
    for (int j = 0; j < 4; j++) {
        const int col = bn + wn + 8 * j + 2 * tig;
        const float b0 = bias[col];
        const float b1 = bias[col + 1];
#pragma unroll
        for (int i = 0; i < 4; i++) {
            const int row = bm + wm + 16 * i + g;
            const float2 v0 = make_float2(acc[i][j][0] + b0, acc[i][j][1] + b1);
            const float2 v1 = make_float2(acc[i][j][2] + b0, acc[i][j][3] + b1);
            if (MODE == 0) {
                *(float2*)&Cout[(size_t)row * N + col] = v0;
                *(float2*)&Cout[(size_t)(row + 8) * N + col] = v1;
            } else {
                const int h_ = col >> 6;
                const int d_ = col & (HD - 1);   // even -> col+1 same head
                const int b0_ = row >> 11;
                const int t0_ = row & (T_SEQ - 1);
                const int b1_ = (row + 8) >> 11;
                const int t1_ = (row + 8) & (T_SEQ - 1);
                *(float2*)&Cout[(((size_t)b0_ * NH + h_) * T_SEQ + t0_) * HD + d_] = v0;
                *(float2*)&Cout[(((size_t)b1_ * NH + h_) * T_SEQ + t1_) * HD + d_] = v1;
            }
        }
    }
}

// ---------------------------------------------------------------------------
// Flash attention (fp32, causal). Block = 64 queries x full D=64.
// 256 threads as 16x16, 4x4 micro-tiles. Online softmax.
// ---------------------------------------------------------------------------
#define APAD 68
#define ATTN_SMEM (4 * 64 * APAD * (int)sizeof(float))  // 69632 B

__global__ __launch_bounds__(256) void attn_kernel(
    const float* __restrict__ Q, const float* __restrict__ K,
    const float* __restrict__ V, float* __restrict__ Y)
{
    extern __shared__ float sm[];
    float* Qts = sm;                  // [d][row]
    float* Kts = sm + 64 * APAD;      // [d][key]
    float* Vs  = sm + 2 * 64 * APAD;  // [key][d]
    float* Ps  = sm + 3 * 64 * APAD;  // [row][key]

    const int tid = threadIdx.x;
    const int tx = tid & 15;
    const int ty = tid >> 4;
    const int bh = blockIdx.y;
    const int qb = blockIdx.x;
    const int q0 = qb * 64;

    const float* Qg = Q + ((size_t)bh * T_SEQ + q0) * HD;
    const float* Kg = K + (size_t)bh * T_SEQ * HD;
    const float* Vg = V + (size_t)bh * T_SEQ * HD;

#pragma unroll
    for (int r = 0; r < 4; r++) {
        const int idx = tid + r * 256;
        const int row = idx >> 4;
        const int d4  = (idx & 15) << 2;
        const float4 v = *(const float4*)(Qg + row * HD + d4);
        Qts[(d4 + 0) * APAD + row] = v.x;
        Qts[(d4 + 1) * APAD + row] = v.y;
        Qts[(d4 + 2) * APAD + row] = v.z;
        Qts[(d4 + 3) * APAD + row] = v.w;
    }

    float o[4][4];
    float m_i[4], l_i[4];
#pragma unroll
    for (int i = 0; i < 4; i++) {
        m_i[i] = -1e30f;
        l_i[i] = 0.f;
#pragma unroll
        for (int d = 0; d < 4; d++) o[i][d] = 0.f;
    }

    for (int j = 0; j <= qb; j++) {
        __syncthreads();
        const float* Kj = Kg + (size_t)j * 64 * HD;
        const float* Vj = Vg + (size_t)j * 64 * HD;
#pragma unroll
        for (int r = 0; r < 4; r++) {
            const int idx = tid + r * 256;
            const int row = idx >> 4;
            const int d4  = (idx & 15) << 2;
            const float4 kv = *(const float4*)(Kj + row * HD + d4);
            Kts[(d4 + 0) * APAD + row] = kv.x;
            Kts[(d4 + 1) * APAD + row] = kv.y;
            Kts[(d4 + 2) * APAD + row] = kv.z;
            Kts[(d4 + 3) * APAD + row] = kv.w;
            const float4 vv = *(const float4*)(Vj + row * HD + d4);
            *(float4*)&Vs[row * APAD + d4] = vv;
        }
        __syncthreads();

        float s[4][4];
#pragma unroll
        for (int i = 0; i < 4; i++)
#pragma unroll
            for (int jj = 0; jj < 4; jj++) s[i][jj] = 0.f;

#pragma unroll 8
        for (int kk = 0; kk < 64; kk++) {
            const float a0 = Qts[kk * APAD + ty * 4 + 0];
            const float a1 = Qts[kk * APAD + ty * 4 + 1];
            const float a2 = Qts[kk * APAD + ty * 4 + 2];
            const float a3 = Qts[kk * APAD + ty * 4 + 3];
            const float4 bb = *(const float4*)&Kts[kk * APAD + tx * 4];
            s[0][0] += a0 * bb.x; s[0][1] += a0 * bb.y; s[0][2] += a0 * bb.z; s[0][3] += a0 * bb.w;
            s[1][0] += a1 * bb.x; s[1][1] += a1 * bb.y; s[1][2] += a1 * bb.z; s[1][3] += a1 * bb.w;
            s[2][0] += a2 * bb.x; s[2][1] += a2 * bb.y; s[2][2] += a2 * bb.z; s[2][3] += a2 * bb.w;
            s[3][0] += a3 * bb.x; s[3][1] += a3 * bb.y; s[3][2] += a3 * bb.z; s[3][3] += a3 * bb.w;
        }

#pragma unroll
        for (int i = 0; i < 4; i++)
#pragma unroll
            for (int jj = 0; jj < 4; jj++) s[i][jj] *= 0.125f;
        if (j == qb) {
#pragma unroll
            for (int i = 0; i < 4; i++)
#pragma unroll
                for (int jj = 0; jj < 4; jj++)
                    if (tx * 4 + jj > ty * 4 + i) s[i][jj] = -1e30f;
        }

#pragma unroll
        for (int i = 0; i < 4; i++) {
            float mv = fmaxf(fmaxf(s[i][0], s[i][1]), fmaxf(s[i][2], s[i][3]));
            mv = fmaxf(mv, __shfl_xor_sync(0xffffffffu, mv, 1));
            mv = fmaxf(mv, __shfl_xor_sync(0xffffffffu, mv, 2));
            mv = fmaxf(mv, __shfl_xor_sync(0xffffffffu, mv, 4));
            mv = fmaxf(mv, __shfl_xor_sync(0xffffffffu, mv, 8));
            const float mn = fmaxf(m_i[i], mv);
            const float alpha = __expf(m_i[i] - mn);
            m_i[i] = mn;
            float rs = 0.f;
#pragma unroll
            for (int jj = 0; jj < 4; jj++) {
                const float p = __expf(s[i][jj] - mn);
                Ps[(ty * 4 + i) * APAD + tx * 4 + jj] = p;
                rs += p;
            }
            rs += __shfl_xor_sync(0xffffffffu, rs, 1);
            rs += __shfl_xor_sync(0xffffffffu, rs, 2);
            rs += __shfl_xor_sync(0xffffffffu, rs, 4);
            rs += __shfl_xor_sync(0xffffffffu, rs, 8);
            l_i[i] = l_i[i] * alpha + rs;
#pragma unroll
            for (int d = 0; d < 4; d++) o[i][d] *= alpha;
        }
        __syncthreads();

#pragma unroll 8
        for (int c = 0; c < 64; c++) {
            const float4 bb = *(const float4*)&Vs[c * APAD + tx * 4];
            const float a0 = Ps[(ty * 4 + 0) * APAD + c];
            const float a1 = Ps[(ty * 4 + 1) * APAD + c];
            const float a2 = Ps[(ty * 4 + 2) * APAD + c];
            const float a3 = Ps[(ty * 4 + 3) * APAD + c];
            o[0][0] += a0 * bb.x; o[0][1] += a0 * bb.y; o[0][2] += a0 * bb.z; o[0][3] += a0 * bb.w;
            o[1][0] += a1 * bb.x; o[1][1] += a1 * bb.y; o[1][2] += a1 * bb.z; o[1][3] += a1 * bb.w;
            o[2][0] += a2 * bb.x; o[2][1] += a2 * bb.y; o[2][2] += a2 * bb.z; o[2][3] += a2 * bb.w;
            o[3][0] += a3 * bb.x; o[3][1] += a3 * bb.y; o[3][2] += a3 * bb.z; o[3][3] += a3 * bb.w;
        }
    }

    const int b_ = bh >> 4;
    const int h_ = bh & 15;
#pragma unroll
    for (int i = 0; i < 4; i++) {
        const int t_ = q0 + ty * 4 + i;
        const float inv = 1.0f / l_i[i];
        const float4 vo = make_float4(o[i][0] * inv, o[i][1] * inv,
                                      o[i][2] * inv, o[i][3] * inv);
        *(float4*)&Y[((size_t)b_ * T_SEQ + t_) * C_EMB + h_ * HD + tx * 4] = vo;
    }
}

// ---------------------------------------------------------------------------
extern "C" void kernel_launch(void* const* d_in, const int* in_sizes, int n_in,
                              void* d_out, int out_size)
{
    const float* x  = (const float*)d_in[0];
    const float* Wq = (const float*)d_in[1];
    const float* bq = (const float*)d_in[2];
    const float* Wk = (const float*)d_in[3];
    const float* bk = (const float*)d_in[4];
    const float* Wv = (const float*)d_in[5];
    const float* bv = (const float*)d_in[6];
    const float* Wp = (const float*)d_in[7];
    const float* bp = (const float*)d_in[8];
    float* out = (float*)d_out;

    float *Qp, *Kp, *Vp, *Yp;
    cudaGetSymbolAddress((void**)&Qp, g_Q);
    cudaGetSymbolAddress((void**)&Kp, g_K);
    cudaGetSymbolAddress((void**)&Vp, g_V);
    cudaGetSymbolAddress((void**)&Yp, g_Yatt);

    cudaFuncSetAttribute(attn_kernel,
                         cudaFuncAttributeMaxDynamicSharedMemorySize, ATTN_SMEM);

    const dim3 gg(C_EMB / BN, M_ROWS / BM);  // (8, 64)
    gemm_tf32_bias<1><<<gg, 256>>>(x, Wq, bq, Qp, M_ROWS, C_EMB, C_EMB);
    gemm_tf32_bias<1><<<gg, 256>>>(x, Wk, bk, Kp, M_ROWS, C_EMB, C_EMB);
    gemm_tf32_bias<1><<<gg, 256>>>(x, Wv, bv, Vp, M_ROWS, C_EMB, C_EMB);

    attn_kernel<<<dim3(T_SEQ / 64, BATCH * NH), 256, ATTN_SMEM>>>(Qp, Kp, Vp, Yp);

    gemm_tf32_bias<0><<<gg, 256>>>(Yp, Wp, bp, out, M_ROWS, C_EMB, C_EMB);
}

// round 4
// speedup vs baseline: 3.1068x; 1.7902x over previous
#include <cuda_runtime.h>
#include <cstdint>

#define T_SEQ   2048
#define NH      16
#define HD      64
#define C_EMB   1024
#define BATCH   4
#define M_ROWS  (BATCH * T_SEQ)   // 8192

// Scratch (allocation-free rule: __device__ globals)
__device__ float g_Q[(size_t)M_ROWS * C_EMB];
__device__ float g_K[(size_t)M_ROWS * C_EMB];
__device__ float g_V[(size_t)M_ROWS * C_EMB];
__device__ float g_Yatt[(size_t)M_ROWS * C_EMB];

__device__ __forceinline__ uint32_t f2tf32(float x) {
    uint32_t r;
    asm("cvt.rna.tf32.f32 %0, %1;" : "=r"(r) : "f"(x));
    return r;
}

__device__ __forceinline__ void mma_tf32(float* c, const uint32_t* a, const uint32_t* b) {
    asm volatile(
        "mma.sync.aligned.m16n8k8.row.col.f32.tf32.tf32.f32 "
        "{%0,%1,%2,%3}, {%4,%5,%6,%7}, {%8,%9}, {%0,%1,%2,%3};"
        : "+f"(c[0]), "+f"(c[1]), "+f"(c[2]), "+f"(c[3])
        : "r"(a[0]), "r"(a[1]), "r"(a[2]), "r"(a[3]), "r"(b[0]), "r"(b[1]));
}

// ---------------------------------------------------------------------------
// tf32 tensor-core GEMM: C = A[M,K] @ B[K,N] + bias  (unchanged from R3)
// MODE 0: row-major [M,N].  MODE 1: QKV scatter to [B,H,T,D].
// ---------------------------------------------------------------------------
#define BM 128
#define BN 128
#define BK 16
#define LDST 136   // BM + 8 pad

template <int MODE>
__global__ __launch_bounds__(256) void gemm_tf32_bias(
    const float* __restrict__ A, const float* __restrict__ B,
    const float* __restrict__ bias, float* __restrict__ Cout,
    int M, int N, int K)
{
    __shared__ uint32_t As[BK][LDST];
    __shared__ uint32_t Bs[BK][LDST];

    const int tid  = threadIdx.x;
    const int bm   = blockIdx.y * BM;
    const int bn   = blockIdx.x * BN;
    const int wid  = tid >> 5;
    const int lane = tid & 31;
    const int g    = lane >> 2;
    const int tig  = lane & 3;
    const int wm   = (wid & 1) * 64;
    const int wn   = (wid >> 1) * 32;

    const int a_m0 = tid >> 2;              const int a_k0 = (tid & 3) << 2;
    const int a_m1 = (tid + 256) >> 2;      const int a_k1 = ((tid + 256) & 3) << 2;
    const int b_k0 = tid >> 5;              const int b_n0 = (tid & 31) << 2;
    const int b_k1 = (tid + 256) >> 5;      const int b_n1 = ((tid + 256) & 31) << 2;

    const float* Ap0 = A + (size_t)(bm + a_m0) * K + a_k0;
    const float* Ap1 = A + (size_t)(bm + a_m1) * K + a_k1;
    const float* Bp0 = B + (size_t)b_k0 * N + bn + b_n0;
    const float* Bp1 = B + (size_t)b_k1 * N + bn + b_n1;

    float4 av0 = *(const float4*)Ap0;
    float4 av1 = *(const float4*)Ap1;
    float4 bv0 = *(const float4*)Bp0;
    float4 bv1 = *(const float4*)Bp1;

    float acc[4][4][4];
#pragma unroll
    for (int i = 0; i < 4; i++)
#pragma unroll
        for (int j = 0; j < 4; j++)
#pragma unroll
            for (int r = 0; r < 4; r++) acc[i][j][r] = 0.f;

    for (int k0 = 0; k0 < K; k0 += BK) {
        As[a_k0 + 0][a_m0] = f2tf32(av0.x);
        As[a_k0 + 1][a_m0] = f2tf32(av0.y);
        As[a_k0 + 2][a_m0] = f2tf32(av0.z);
        As[a_k0 + 3][a_m0] = f2tf32(av0.w);
        As[a_k1 + 0][a_m1] = f2tf32(av1.x);
        As[a_k1 + 1][a_m1] = f2tf32(av1.y);
        As[a_k1 + 2][a_m1] = f2tf32(av1.z);
        As[a_k1 + 3][a_m1] = f2tf32(av1.w);
        {
            uint4 t0 = make_uint4(f2tf32(bv0.x), f2tf32(bv0.y), f2tf32(bv0.z), f2tf32(bv0.w));
            uint4 t1 = make_uint4(f2tf32(bv1.x), f2tf32(bv1.y), f2tf32(bv1.z), f2tf32(bv1.w));
            *(uint4*)&Bs[b_k0][b_n0] = t0;
            *(uint4*)&Bs[b_k1][b_n1] = t1;
        }
        __syncthreads();

        if (k0 + BK < K) {
            Ap0 += BK; Ap1 += BK;
            Bp0 += (size_t)BK * N; Bp1 += (size_t)BK * N;
            av0 = *(const float4*)Ap0;
            av1 = *(const float4*)Ap1;
            bv0 = *(const float4*)Bp0;
            bv1 = *(const float4*)Bp1;
        }

#pragma unroll
        for (int ks = 0; ks < BK; ks += 8) {
            uint32_t af[4][4], bf[4][2];
#pragma unroll
            for (int i = 0; i < 4; i++) {
                const int mb = wm + 16 * i;
                af[i][0] = As[ks + tig][mb + g];
                af[i][1] = As[ks + tig][mb + g + 8];
                af[i][2] = As[ks + tig + 4][mb + g];
                af[i][3] = As[ks + tig + 4][mb + g + 8];
            }
#pragma unroll
            for (int j = 0; j < 4; j++) {
                const int nb = wn + 8 * j;
                bf[j][0] = Bs[ks + tig][nb + g];
                bf[j][1] = Bs[ks + tig + 4][nb + g];
            }
#pragma unroll
            for (int i = 0; i < 4; i++)
#pragma unroll
                for (int j = 0; j < 4; j++)
                    mma_tf32(acc[i][j], af[i], bf[j]);
        }
        __syncthreads();
    }

#pragma unroll
    for (int j = 0; j < 4; j++) {
        const int col = bn + wn + 8 * j + 2 * tig;
        const float b0 = bias[col];
        const float b1 = bias[col + 1];
#pragma unroll
        for (int i = 0; i < 4; i++) {
            const int row = bm + wm + 16 * i + g;
            const float2 v0 = make_float2(acc[i][j][0] + b0, acc[i][j][1] + b1);
            const float2 v1 = make_float2(acc[i][j][2] + b0, acc[i][j][3] + b1);
            if (MODE == 0) {
                *(float2*)&Cout[(size_t)row * N + col] = v0;
                *(float2*)&Cout[(size_t)(row + 8) * N + col] = v1;
            } else {
                const int h_ = col >> 6;
                const int d_ = col & (HD - 1);
                const int b0_ = row >> 11;
                const int t0_ = row & (T_SEQ - 1);
                const int b1_ = (row + 8) >> 11;
                const int t1_ = (row + 8) & (T_SEQ - 1);
                *(float2*)&Cout[(((size_t)b0_ * NH + h_) * T_SEQ + t0_) * HD + d_] = v0;
                *(float2*)&Cout[(((size_t)b1_ * NH + h_) * T_SEQ + t1_) * HD + d_] = v1;
            }
        }
    }
}

// ---------------------------------------------------------------------------
// Tensor-core flash attention (tf32 mma, fp32 softmax/accum, causal).
// 128 queries/CTA, 64-key tiles, 8 warps x 16 query rows each.
// ---------------------------------------------------------------------------
#define QS_STRIDE 68
#define KS_STRIDE 68
#define VS_STRIDE 72
#define ATTN_SMEM ((128 * QS_STRIDE + 64 * KS_STRIDE + 64 * VS_STRIDE) * 4)  // 70656 B

__global__ __launch_bounds__(256) void attn_tc_kernel(
    const float* __restrict__ Q, const float* __restrict__ K,
    const float* __restrict__ V, float* __restrict__ Y)
{
    extern __shared__ uint32_t smu[];
    uint32_t* Qsm = smu;                          // [128][68] tf32 (pre-scaled)
    uint32_t* Ksm = smu + 128 * QS_STRIDE;        // [64][68]
    uint32_t* Vsm = Ksm + 64 * KS_STRIDE;         // [64][72]

    const int tid  = threadIdx.x;
    const int w    = tid >> 5;
    const int lane = tid & 31;
    const int g    = lane >> 2;
    const int tig  = lane & 3;
    const int bh   = blockIdx.y;
    const int qb   = blockIdx.x;
    const int q0   = qb * 128;

    const float* Qg = Q + ((size_t)bh * T_SEQ + q0) * HD;
    const float* Kg = K + (size_t)bh * T_SEQ * HD;
    const float* Vg = V + (size_t)bh * T_SEQ * HD;

    // Stage Q tile (scaled by 1/sqrt(D)=0.125, tf32)
#pragma unroll
    for (int r = 0; r < 8; r++) {
        const int idx = tid + r * 256;        // 2048 float4 chunks
        const int row = idx >> 4;
        const int d4  = (idx & 15) << 2;
        const float4 v = *(const float4*)(Qg + row * HD + d4);
        uint32_t* p = &Qsm[row * QS_STRIDE + d4];
        p[0] = f2tf32(v.x * 0.125f);
        p[1] = f2tf32(v.y * 0.125f);
        p[2] = f2tf32(v.z * 0.125f);
        p[3] = f2tf32(v.w * 0.125f);
    }
    __syncthreads();

    // Q fragments (persistent): warp w owns rows 16w..16w+15
    uint32_t qf[8][4];
    {
        const int r0 = 16 * w + g;
#pragma unroll
        for (int ks = 0; ks < 8; ks++) {
            qf[ks][0] = Qsm[r0 * QS_STRIDE + 8 * ks + tig];
            qf[ks][1] = Qsm[(r0 + 8) * QS_STRIDE + 8 * ks + tig];
            qf[ks][2] = Qsm[r0 * QS_STRIDE + 8 * ks + tig + 4];
            qf[ks][3] = Qsm[(r0 + 8) * QS_STRIDE + 8 * ks + tig + 4];
        }
    }

    float o[8][4];
#pragma unroll
    for (int j = 0; j < 8; j++)
#pragma unroll
        for (int r = 0; r < 4; r++) o[j][r] = 0.f;
    float m_lo = -1e30f, m_hi = -1e30f, l_lo = 0.f, l_hi = 0.f;

    const int row_lo = q0 + 16 * w + g;
    const int row_hi = row_lo + 8;
    const int row_max_w = q0 + 16 * w + 15;
    const int qbase = lane & 28;
    const int srcA = qbase + (tig >> 1);
    const int srcB = srcA + 2;

    for (int s0 = 0; s0 < q0 + 128; s0 += 64) {
        __syncthreads();
        // Load K,V tiles (64x64 each), tf32
#pragma unroll
        for (int r = 0; r < 4; r++) {
            const int idx = tid + r * 256;
            const int row = idx >> 4;
            const int d4  = (idx & 15) << 2;
            const float4 kv = *(const float4*)(Kg + (size_t)(s0 + row) * HD + d4);
            uint32_t* pk = &Ksm[row * KS_STRIDE + d4];
            pk[0] = f2tf32(kv.x); pk[1] = f2tf32(kv.y);
            pk[2] = f2tf32(kv.z); pk[3] = f2tf32(kv.w);
            const float4 vv = *(const float4*)(Vg + (size_t)(s0 + row) * HD + d4);
            uint32_t* pv = &Vsm[row * VS_STRIDE + d4];
            pv[0] = f2tf32(vv.x); pv[1] = f2tf32(vv.y);
            pv[2] = f2tf32(vv.z); pv[3] = f2tf32(vv.w);
        }
        __syncthreads();

        if (s0 > row_max_w) continue;  // fully masked for this warp's rows

        // S = Q @ K^T : 8 n-tiles of 8 keys, 8 k-steps over D
        float s_[8][4];
#pragma unroll
        for (int j = 0; j < 8; j++)
#pragma unroll
            for (int r = 0; r < 4; r++) s_[j][r] = 0.f;

#pragma unroll
        for (int ks = 0; ks < 8; ks++) {
#pragma unroll
            for (int j = 0; j < 8; j++) {
                uint32_t b[2];
                b[0] = Ksm[(8 * j + g) * KS_STRIDE + 8 * ks + tig];
                b[1] = Ksm[(8 * j + g) * KS_STRIDE + 8 * ks + tig + 4];
                mma_tf32(s_[j], qf[ks], b);
            }
        }

        // causal mask (only tiles intersecting the diagonal for this warp)
        if (s0 + 63 > q0 + 16 * w) {
#pragma unroll
            for (int j = 0; j < 8; j++) {
                const int c0 = s0 + 8 * j + 2 * tig;
                if (c0 > row_lo)     s_[j][0] = -1e30f;
                if (c0 + 1 > row_lo) s_[j][1] = -1e30f;
                if (c0 > row_hi)     s_[j][2] = -1e30f;
                if (c0 + 1 > row_hi) s_[j][3] = -1e30f;
            }
        }

        // online softmax (rows g and g+8, reduced across the quad)
        float t_lo = -1e30f, t_hi = -1e30f;
#pragma unroll
        for (int j = 0; j < 8; j++) {
            t_lo = fmaxf(t_lo, fmaxf(s_[j][0], s_[j][1]));
            t_hi = fmaxf(t_hi, fmaxf(s_[j][2], s_[j][3]));
        }
        t_lo = fmaxf(t_lo, __shfl_xor_sync(0xffffffffu, t_lo, 1));
        t_lo = fmaxf(t_lo, __shfl_xor_sync(0xffffffffu, t_lo, 2));
        t_hi = fmaxf(t_hi, __shfl_xor_sync(0xffffffffu, t_hi, 1));
        t_hi = fmaxf(t_hi, __shfl_xor_sync(0xffffffffu, t_hi, 2));

        const float mn_lo = fmaxf(m_lo, t_lo);
        const float mn_hi = fmaxf(m_hi, t_hi);
        const float a_lo = __expf(m_lo - mn_lo);
        const float a_hi = __expf(m_hi - mn_hi);
        m_lo = mn_lo; m_hi = mn_hi;

        float rs_lo = 0.f, rs_hi = 0.f;
#pragma unroll
        for (int j = 0; j < 8; j++) {
            const float p0 = __expf(s_[j][0] - mn_lo);
            const float p1 = __expf(s_[j][1] - mn_lo);
            const float p2 = __expf(s_[j][2] - mn_hi);
            const float p3 = __expf(s_[j][3] - mn_hi);
            rs_lo += p0 + p1;
            rs_hi += p2 + p3;
            s_[j][0] = __uint_as_float(f2tf32(p0));
            s_[j][1] = __uint_as_float(f2tf32(p1));
            s_[j][2] = __uint_as_float(f2tf32(p2));
            s_[j][3] = __uint_as_float(f2tf32(p3));
        }
        rs_lo += __shfl_xor_sync(0xffffffffu, rs_lo, 1);
        rs_lo += __shfl_xor_sync(0xffffffffu, rs_lo, 2);
        rs_hi += __shfl_xor_sync(0xffffffffu, rs_hi, 1);
        rs_hi += __shfl_xor_sync(0xffffffffu, rs_hi, 2);
        l_lo = l_lo * a_lo + rs_lo;
        l_hi = l_hi * a_hi + rs_hi;

#pragma unroll
        for (int jd = 0; jd < 8; jd++) {
            o[jd][0] *= a_lo; o[jd][1] *= a_lo;
            o[jd][2] *= a_hi; o[jd][3] *= a_hi;
        }

        // O += P @ V : permute P C-frag -> A-frag via quad shuffles
#pragma unroll
        for (int ks = 0; ks < 8; ks++) {
            const float p0 = s_[ks][0], p1 = s_[ks][1];
            const float p2 = s_[ks][2], p3 = s_[ks][3];
            const float u0 = __shfl_sync(0xffffffffu, p0, srcA);
            const float u1 = __shfl_sync(0xffffffffu, p1, srcA);
            const float v0 = __shfl_sync(0xffffffffu, p2, srcA);
            const float v1 = __shfl_sync(0xffffffffu, p3, srcA);
            const float x0 = __shfl_sync(0xffffffffu, p0, srcB);
            const float x1 = __shfl_sync(0xffffffffu, p1, srcB);
            const float y0 = __shfl_sync(0xffffffffu, p2, srcB);
            const float y1 = __shfl_sync(0xffffffffu, p3, srcB);
            uint32_t a[4];
            a[0] = __float_as_uint((tig & 1) ? u1 : u0);
            a[1] = __float_as_uint((tig & 1) ? v1 : v0);
            a[2] = __float_as_uint((tig & 1) ? x1 : x0);
            a[3] = __float_as_uint((tig & 1) ? y1 : y0);
#pragma unroll
            for (int jd = 0; jd < 8; jd++) {
                uint32_t b[2];
                b[0] = Vsm[(8 * ks + tig) * VS_STRIDE + 8 * jd + g];
                b[1] = Vsm[(8 * ks + tig + 4) * VS_STRIDE + 8 * jd + g];
                mma_tf32(o[jd], a, b);
            }
        }
    }

    // Normalize + write Y in [B,T,C] layout
    const float il_lo = 1.0f / l_lo;
    const float il_hi = 1.0f / l_hi;
    const int b_ = bh >> 4;
    const int h_ = bh & 15;
    float* Yb = Y + (size_t)b_ * T_SEQ * C_EMB + h_ * HD;
#pragma unroll
    for (int jd = 0; jd < 8; jd++) {
        const int d = 8 * jd + 2 * tig;
        const float2 vlo = make_float2(o[jd][0] * il_lo, o[jd][1] * il_lo);
        const float2 vhi = make_float2(o[jd][2] * il_hi, o[jd][3] * il_hi);
        *(float2*)&Yb[(size_t)row_lo * C_EMB + d] = vlo;
        *(float2*)&Yb[(size_t)row_hi * C_EMB + d] = vhi;
    }
}

// ---------------------------------------------------------------------------
extern "C" void kernel_launch(void* const* d_in, const int* in_sizes, int n_in,
                              void* d_out, int out_size)
{
    const float* x  = (const float*)d_in[0];
    const float* Wq = (const float*)d_in[1];
    const float* bq = (const float*)d_in[2];
    const float* Wk = (const float*)d_in[3];
    const float* bk = (const float*)d_in[4];
    const float* Wv = (const float*)d_in[5];
    const float* bv = (const float*)d_in[6];
    const float* Wp = (const float*)d_in[7];
    const float* bp = (const float*)d_in[8];
    float* out = (float*)d_out;

    float *Qp, *Kp, *Vp, *Yp;
    cudaGetSymbolAddress((void**)&Qp, g_Q);
    cudaGetSymbolAddress((void**)&Kp, g_K);
    cudaGetSymbolAddress((void**)&Vp, g_V);
    cudaGetSymbolAddress((void**)&Yp, g_Yatt);

    cudaFuncSetAttribute(attn_tc_kernel,
                         cudaFuncAttributeMaxDynamicSharedMemorySize, ATTN_SMEM);

    const dim3 gg(C_EMB / BN, M_ROWS / BM);  // (8, 64)
    gemm_tf32_bias<1><<<gg, 256>>>(x, Wq, bq, Qp, M_ROWS, C_EMB, C_EMB);
    gemm_tf32_bias<1><<<gg, 256>>>(x, Wk, bk, Kp, M_ROWS, C_EMB, C_EMB);
    gemm_tf32_bias<1><<<gg, 256>>>(x, Wv, bv, Vp, M_ROWS, C_EMB, C_EMB);

    attn_tc_kernel<<<dim3(T_SEQ / 128, BATCH * NH), 256, ATTN_SMEM>>>(Qp, Kp, Vp, Yp);

    gemm_tf32_bias<0><<<gg, 256>>>(Yp, Wp, bp, out, M_ROWS, C_EMB, C_EMB);
}

// round 5
// speedup vs baseline: 3.5910x; 1.1559x over previous
#include <cuda_runtime.h>
#include <cstdint>

#define T_SEQ   2048
#define NH      16
#define HD      64
#define C_EMB   1024
#define BATCH   4
#define M_ROWS  (BATCH * T_SEQ)   // 8192

// Scratch (allocation-free rule: __device__ globals)
__device__ float g_Q[(size_t)M_ROWS * C_EMB];
__device__ float g_K[(size_t)M_ROWS * C_EMB];
__device__ float g_V[(size_t)M_ROWS * C_EMB];
__device__ float g_Yatt[(size_t)M_ROWS * C_EMB];

__device__ __forceinline__ uint32_t f2tf32(float x) {
    uint32_t r;
    asm("cvt.rna.tf32.f32 %0, %1;" : "=r"(r) : "f"(x));
    return r;
}

__device__ __forceinline__ void mma_tf32(float* c, const uint32_t* a, const uint32_t* b) {
    asm volatile(
        "mma.sync.aligned.m16n8k8.row.col.f32.tf32.tf32.f32 "
        "{%0,%1,%2,%3}, {%4,%5,%6,%7}, {%8,%9}, {%0,%1,%2,%3};"
        : "+f"(c[0]), "+f"(c[1]), "+f"(c[2]), "+f"(c[3])
        : "r"(a[0]), "r"(a[1]), "r"(a[2]), "r"(a[3]), "r"(b[0]), "r"(b[1]));
}

// ---------------------------------------------------------------------------
// tf32 tensor-core GEMM body: C = A[M,K] @ B[K,N] + bias
// 128x128x16 tile, 8 warps, warp tile 64x32. Double-buffered smem,
// ONE __syncthreads per k-tile (end-of-iter barrier protects buffer reuse).
// MODE 0: row-major [M,N].  MODE 1: QKV scatter to [B,H,T,D].
// ---------------------------------------------------------------------------
#define BM 128
#define BN 128
#define BK 16
#define LDST 136   // BM + 8 pad

template <int MODE>
__device__ __forceinline__ void gemm_body(
    const float* __restrict__ A, const float* __restrict__ B,
    const float* __restrict__ bias, float* __restrict__ Cout,
    int M, int N, int K)
{
    __shared__ uint32_t SA[2][BK][LDST];
    __shared__ uint32_t SB[2][BK][LDST];

    const int tid  = threadIdx.x;
    const int bm   = blockIdx.y * BM;
    const int bn   = blockIdx.x * BN;
    const int wid  = tid >> 5;
    const int lane = tid & 31;
    const int g    = lane >> 2;
    const int tig  = lane & 3;
    const int wm   = (wid & 1) * 64;
    const int wn   = (wid >> 1) * 32;

    const int a_m0 = tid >> 2;              const int a_k0 = (tid & 3) << 2;
    const int a_m1 = (tid + 256) >> 2;      const int a_k1 = ((tid + 256) & 3) << 2;
    const int b_k0 = tid >> 5;              const int b_n0 = (tid & 31) << 2;
    const int b_k1 = (tid + 256) >> 5;      const int b_n1 = ((tid + 256) & 31) << 2;

    const float* Ap0 = A + (size_t)(bm + a_m0) * K + a_k0;
    const float* Ap1 = A + (size_t)(bm + a_m1) * K + a_k1;
    const float* Bp0 = B + (size_t)b_k0 * N + bn + b_n0;
    const float* Bp1 = B + (size_t)b_k1 * N + bn + b_n1;

    float4 av0 = *(const float4*)Ap0;
    float4 av1 = *(const float4*)Ap1;
    float4 bv0 = *(const float4*)Bp0;
    float4 bv1 = *(const float4*)Bp1;

    float acc[4][4][4];
#pragma unroll
    for (int i = 0; i < 4; i++)
#pragma unroll
        for (int j = 0; j < 4; j++)
#pragma unroll
            for (int r = 0; r < 4; r++) acc[i][j][r] = 0.f;

#define STORE_TILE(bf)                                                        \
    do {                                                                      \
        SA[bf][a_k0 + 0][a_m0] = f2tf32(av0.x);                               \
        SA[bf][a_k0 + 1][a_m0] = f2tf32(av0.y);                               \
        SA[bf][a_k0 + 2][a_m0] = f2tf32(av0.z);                               \
        SA[bf][a_k0 + 3][a_m0] = f2tf32(av0.w);                               \
        SA[bf][a_k1 + 0][a_m1] = f2tf32(av1.x);                               \
        SA[bf][a_k1 + 1][a_m1] = f2tf32(av1.y);                               \
        SA[bf][a_k1 + 2][a_m1] = f2tf32(av1.z);                               \
        SA[bf][a_k1 + 3][a_m1] = f2tf32(av1.w);                               \
        *(uint4*)&SB[bf][b_k0][b_n0] =                                        \
            make_uint4(f2tf32(bv0.x), f2tf32(bv0.y), f2tf32(bv0.z), f2tf32(bv0.w)); \
        *(uint4*)&SB[bf][b_k1][b_n1] =                                        \
            make_uint4(f2tf32(bv1.x), f2tf32(bv1.y), f2tf32(bv1.z), f2tf32(bv1.w)); \
    } while (0)

    STORE_TILE(0);
    __syncthreads();

    int buf = 0;
    for (int k0 = 0; k0 < K; k0 += BK, buf ^= 1) {
        const bool has_next = (k0 + BK < K);
        if (has_next) {
            Ap0 += BK; Ap1 += BK;
            Bp0 += (size_t)BK * N; Bp1 += (size_t)BK * N;
            av0 = *(const float4*)Ap0;
            av1 = *(const float4*)Ap1;
            bv0 = *(const float4*)Bp0;
            bv1 = *(const float4*)Bp1;
        }

#pragma unroll
        for (int ks = 0; ks < BK; ks += 8) {
            uint32_t af[4][4], bfr[4][2];
#pragma unroll
            for (int i = 0; i < 4; i++) {
                const int mb = wm + 16 * i;
                af[i][0] = SA[buf][ks + tig][mb + g];
                af[i][1] = SA[buf][ks + tig][mb + g + 8];
                af[i][2] = SA[buf][ks + tig + 4][mb + g];
                af[i][3] = SA[buf][ks + tig + 4][mb + g + 8];
            }
#pragma unroll
            for (int j = 0; j < 4; j++) {
                const int nb = wn + 8 * j;
                bfr[j][0] = SB[buf][ks + tig][nb + g];
                bfr[j][1] = SB[buf][ks + tig + 4][nb + g];
            }
#pragma unroll
            for (int i = 0; i < 4; i++)
#pragma unroll
                for (int j = 0; j < 4; j++)
                    mma_tf32(acc[i][j], af[i], bfr[j]);
        }

        if (has_next) STORE_TILE(buf ^ 1);
        __syncthreads();
    }
#undef STORE_TILE

#pragma unroll
    for (int j = 0; j < 4; j++) {
        const int col = bn + wn + 8 * j + 2 * tig;
        const float b0 = bias[col];
        const float b1 = bias[col + 1];
#pragma unroll
        for (int i = 0; i < 4; i++) {
            const int row = bm + wm + 16 * i + g;
            const float2 v0 = make_float2(acc[i][j][0] + b0, acc[i][j][1] + b1);
            const float2 v1 = make_float2(acc[i][j][2] + b0, acc[i][j][3] + b1);
            if (MODE == 0) {
                *(float2*)&Cout[(size_t)row * N + col] = v0;
                *(float2*)&Cout[(size_t)(row + 8) * N + col] = v1;
            } else {
                const int h_ = col >> 6;
                const int d_ = col & (HD - 1);
                const int b0_ = row >> 11;
                const int t0_ = row & (T_SEQ - 1);
                const int b1_ = (row + 8) >> 11;
                const int t1_ = (row + 8) & (T_SEQ - 1);
                *(float2*)&Cout[(((size_t)b0_ * NH + h_) * T_SEQ + t0_) * HD + d_] = v0;
                *(float2*)&Cout[(((size_t)b1_ * NH + h_) * T_SEQ + t1_) * HD + d_] = v1;
            }
        }
    }
}

// Fused QKV projection: blockIdx.z selects (W, bias, out). One tail wave.
__global__ __launch_bounds__(256) void gemm_qkv_tf32(
    const float* __restrict__ A,
    const float* __restrict__ W0, const float* __restrict__ W1, const float* __restrict__ W2,
    const float* __restrict__ c0, const float* __restrict__ c1, const float* __restrict__ c2,
    float* __restrict__ O0, float* __restrict__ O1, float* __restrict__ O2,
    int M, int N, int K)
{
    const int z = blockIdx.z;
    const float* B    = (z == 0) ? W0 : (z == 1) ? W1 : W2;
    const float* bias = (z == 0) ? c0 : (z == 1) ? c1 : c2;
    float* Cout       = (z == 0) ? O0 : (z == 1) ? O1 : O2;
    gemm_body<1>(A, B, bias, Cout, M, N, K);
}

__global__ __launch_bounds__(256) void gemm_out_tf32(
    const float* __restrict__ A, const float* __restrict__ B,
    const float* __restrict__ bias, float* __restrict__ Cout,
    int M, int N, int K)
{
    gemm_body<0>(A, B, bias, Cout, M, N, K);
}

// ---------------------------------------------------------------------------
// Tensor-core flash attention (tf32 mma, fp32 softmax/accum, causal).
// 128 queries/CTA, 64-key tiles, 8 warps x 16 query rows each.
// Q fragments reloaded from smem per k-step (saves 32 regs -> 2 CTAs/SM).
// ---------------------------------------------------------------------------
#define QS_STRIDE 68
#define KS_STRIDE 68
#define VS_STRIDE 72
#define ATTN_SMEM ((128 * QS_STRIDE + 64 * KS_STRIDE + 64 * VS_STRIDE) * 4)  // 70656 B

__global__ __launch_bounds__(256, 2) void attn_tc_kernel(
    const float* __restrict__ Q, const float* __restrict__ K,
    const float* __restrict__ V, float* __restrict__ Y)
{
    extern __shared__ uint32_t smu[];
    uint32_t* Qsm = smu;                          // [128][68] tf32 (pre-scaled)
    uint32_t* Ksm = smu + 128 * QS_STRIDE;        // [64][68]
    uint32_t* Vsm = Ksm + 64 * KS_STRIDE;         // [64][72]

    const int tid  = threadIdx.x;
    const int w    = tid >> 5;
    const int lane = tid & 31;
    const int g    = lane >> 2;
    const int tig  = lane & 3;
    const int bh   = blockIdx.y;
    const int qb   = blockIdx.x;
    const int q0   = qb * 128;

    const float* Qg = Q + ((size_t)bh * T_SEQ + q0) * HD;
    const float* Kg = K + (size_t)bh * T_SEQ * HD;
    const float* Vg = V + (size_t)bh * T_SEQ * HD;

    // Stage Q tile (scaled by 1/sqrt(D)=0.125, tf32)
#pragma unroll
    for (int r = 0; r < 8; r++) {
        const int idx = tid + r * 256;
        const int row = idx >> 4;
        const int d4  = (idx & 15) << 2;
        const float4 v = *(const float4*)(Qg + row * HD + d4);
        uint32_t* p = &Qsm[row * QS_STRIDE + d4];
        p[0] = f2tf32(v.x * 0.125f);
        p[1] = f2tf32(v.y * 0.125f);
        p[2] = f2tf32(v.z * 0.125f);
        p[3] = f2tf32(v.w * 0.125f);
    }

    float o[8][4];
#pragma unroll
    for (int j = 0; j < 8; j++)
#pragma unroll
        for (int r = 0; r < 4; r++) o[j][r] = 0.f;
    float m_lo = -1e30f, m_hi = -1e30f, l_lo = 0.f, l_hi = 0.f;

    const int r0      = 16 * w + g;       // warp-local row (lo)
    const int row_lo  = q0 + r0;
    const int row_hi  = row_lo + 8;
    const int row_max_w = q0 + 16 * w + 15;
    const int qbase = lane & 28;
    const int srcA  = qbase + (tig >> 1);
    const int srcB  = srcA + 2;

    for (int s0 = 0; s0 < q0 + 128; s0 += 64) {
        __syncthreads();   // also orders initial Q staging before first use
        // Load K,V tiles (64x64 each), tf32
#pragma unroll
        for (int r = 0; r < 4; r++) {
            const int idx = tid + r * 256;
            const int row = idx >> 4;
            const int d4  = (idx & 15) << 2;
            const float4 kv = *(const float4*)(Kg + (size_t)(s0 + row) * HD + d4);
            uint32_t* pk = &Ksm[row * KS_STRIDE + d4];
            pk[0] = f2tf32(kv.x); pk[1] = f2tf32(kv.y);
            pk[2] = f2tf32(kv.z); pk[3] = f2tf32(kv.w);
            const float4 vv = *(const float4*)(Vg + (size_t)(s0 + row) * HD + d4);
            uint32_t* pv = &Vsm[row * VS_STRIDE + d4];
            pv[0] = f2tf32(vv.x); pv[1] = f2tf32(vv.y);
            pv[2] = f2tf32(vv.z); pv[3] = f2tf32(vv.w);
        }
        __syncthreads();

        if (s0 > row_max_w) continue;  // fully masked for this warp's rows

        // S = Q @ K^T : Q fragments loaded from smem per k-step
        float s_[8][4];
#pragma unroll
        for (int j = 0; j < 8; j++)
#pragma unroll
            for (int r = 0; r < 4; r++) s_[j][r] = 0.f;

#pragma unroll
        for (int ks = 0; ks < 8; ks++) {
            uint32_t a[4];
            a[0] = Qsm[r0 * QS_STRIDE + 8 * ks + tig];
            a[1] = Qsm[(r0 + 8) * QS_STRIDE + 8 * ks + tig];
            a[2] = Qsm[r0 * QS_STRIDE + 8 * ks + tig + 4];
            a[3] = Qsm[(r0 + 8) * QS_STRIDE + 8 * ks + tig + 4];
#pragma unroll
            for (int j = 0; j < 8; j++) {
                uint32_t b[2];
                b[0] = Ksm[(8 * j + g) * KS_STRIDE + 8 * ks + tig];
                b[1] = Ksm[(8 * j + g) * KS_STRIDE + 8 * ks + tig + 4];
                mma_tf32(s_[j], a, b);
            }
        }

        // causal mask (only tiles intersecting the diagonal for this warp)
        if (s0 + 63 > q0 + 16 * w) {
#pragma unroll
            for (int j = 0; j < 8; j++) {
                const int c0 = s0 + 8 * j + 2 * tig;
                if (c0 > row_lo)     s_[j][0] = -1e30f;
                if (c0 + 1 > row_lo) s_[j][1] = -1e30f;
                if (c0 > row_hi)     s_[j][2] = -1e30f;
                if (c0 + 1 > row_hi) s_[j][3] = -1e30f;
            }
        }

        // online softmax (rows g and g+8, reduced across the quad)
        float t_lo = -1e30f, t_hi = -1e30f;
#pragma unroll
        for (int j = 0; j < 8; j++) {
            t_lo = fmaxf(t_lo, fmaxf(s_[j][0], s_[j][1]));
            t_hi = fmaxf(t_hi, fmaxf(s_[j][2], s_[j][3]));
        }
        t_lo = fmaxf(t_lo, __shfl_xor_sync(0xffffffffu, t_lo, 1));
        t_lo = fmaxf(t_lo, __shfl_xor_sync(0xffffffffu, t_lo, 2));
        t_hi = fmaxf(t_hi, __shfl_xor_sync(0xffffffffu, t_hi, 1));
        t_hi = fmaxf(t_hi, __shfl_xor_sync(0xffffffffu, t_hi, 2));

        const float mn_lo = fmaxf(m_lo, t_lo);
        const float mn_hi = fmaxf(m_hi, t_hi);
        const float a_lo = __expf(m_lo - mn_lo);
        const float a_hi = __expf(m_hi - mn_hi);
        m_lo = mn_lo; m_hi = mn_hi;

        float rs_lo = 0.f, rs_hi = 0.f;
#pragma unroll
        for (int j = 0; j < 8; j++) {
            const float p0 = __expf(s_[j][0] - mn_lo);
            const float p1 = __expf(s_[j][1] - mn_lo);
            const float p2 = __expf(s_[j][2] - mn_hi);
            const float p3 = __expf(s_[j][3] - mn_hi);
            rs_lo += p0 + p1;
            rs_hi += p2 + p3;
            s_[j][0] = __uint_as_float(f2tf32(p0));
            s_[j][1] = __uint_as_float(f2tf32(p1));
            s_[j][2] = __uint_as_float(f2tf32(p2));
            s_[j][3] = __uint_as_float(f2tf32(p3));
        }
        rs_lo += __shfl_xor_sync(0xffffffffu, rs_lo, 1);
        rs_lo += __shfl_xor_sync(0xffffffffu, rs_lo, 2);
        rs_hi += __shfl_xor_sync(0xffffffffu, rs_hi, 1);
        rs_hi += __shfl_xor_sync(0xffffffffu, rs_hi, 2);
        l_lo = l_lo * a_lo + rs_lo;
        l_hi = l_hi * a_hi + rs_hi;

#pragma unroll
        for (int jd = 0; jd < 8; jd++) {
            o[jd][0] *= a_lo; o[jd][1] *= a_lo;
            o[jd][2] *= a_hi; o[jd][3] *= a_hi;
        }

        // O += P @ V : permute P C-frag -> A-frag via quad shuffles
#pragma unroll
        for (int ks = 0; ks < 8; ks++) {
            const float p0 = s_[ks][0], p1 = s_[ks][1];
            const float p2 = s_[ks][2], p3 = s_[ks][3];
            const float u0 = __shfl_sync(0xffffffffu, p0, srcA);
            const float u1 = __shfl_sync(0xffffffffu, p1, srcA);
            const float v0 = __shfl_sync(0xffffffffu, p2, srcA);
            const float v1 = __shfl_sync(0xffffffffu, p3, srcA);
            const float x0 = __shfl_sync(0xffffffffu, p0, srcB);
            const float x1 = __shfl_sync(0xffffffffu, p1, srcB);
            const float y0 = __shfl_sync(0xffffffffu, p2, srcB);
            const float y1 = __shfl_sync(0xffffffffu, p3, srcB);
            uint32_t a[4];
            a[0] = __float_as_uint((tig & 1) ? u1 : u0);
            a[1] = __float_as_uint((tig & 1) ? v1 : v0);
            a[2] = __float_as_uint((tig & 1) ? x1 : x0);
            a[3] = __float_as_uint((tig & 1) ? y1 : y0);
#pragma unroll
            for (int jd = 0; jd < 8; jd++) {
                uint32_t b[2];
                b[0] = Vsm[(8 * ks + tig) * VS_STRIDE + 8 * jd + g];
                b[1] = Vsm[(8 * ks + tig + 4) * VS_STRIDE + 8 * jd + g];
                mma_tf32(o[jd], a, b);
            }
        }
    }

    // Normalize + write Y in [B,T,C] layout
    const float il_lo = 1.0f / l_lo;
    const float il_hi = 1.0f / l_hi;
    const int b_ = bh >> 4;
    const int h_ = bh & 15;
    float* Yb = Y + (size_t)b_ * T_SEQ * C_EMB + h_ * HD;
#pragma unroll
    for (int jd = 0; jd < 8; jd++) {
        const int d = 8 * jd + 2 * tig;
        const float2 vlo = make_float2(o[jd][0] * il_lo, o[jd][1] * il_lo);
        const float2 vhi = make_float2(o[jd][2] * il_hi, o[jd][3] * il_hi);
        *(float2*)&Yb[(size_t)row_lo * C_EMB + d] = vlo;
        *(float2*)&Yb[(size_t)row_hi * C_EMB + d] = vhi;
    }
}

// ---------------------------------------------------------------------------
extern "C" void kernel_launch(void* const* d_in, const int* in_sizes, int n_in,
                              void* d_out, int out_size)
{
    const float* x  = (const float*)d_in[0];
    const float* Wq = (const float*)d_in[1];
    const float* bq = (const float*)d_in[2];
    const float* Wk = (const float*)d_in[3];
    const float* bk = (const float*)d_in[4];
    const float* Wv = (const float*)d_in[5];
    const float* bv = (const float*)d_in[6];
    const float* Wp = (const float*)d_in[7];
    const float* bp = (const float*)d_in[8];
    float* out = (float*)d_out;

    float *Qp, *Kp, *Vp, *Yp;
    cudaGetSymbolAddress((void**)&Qp, g_Q);
    cudaGetSymbolAddress((void**)&Kp, g_K);
    cudaGetSymbolAddress((void**)&Vp, g_V);
    cudaGetSymbolAddress((void**)&Yp, g_Yatt);

    cudaFuncSetAttribute(attn_tc_kernel,
                         cudaFuncAttributeMaxDynamicSharedMemorySize, ATTN_SMEM);

    const dim3 gqkv(C_EMB / BN, M_ROWS / BM, 3);  // (8, 64, 3)
    gemm_qkv_tf32<<<gqkv, 256>>>(x, Wq, Wk, Wv, bq, bk, bv, Qp, Kp, Vp,
                                 M_ROWS, C_EMB, C_EMB);

    attn_tc_kernel<<<dim3(T_SEQ / 128, BATCH * NH), 256, ATTN_SMEM>>>(Qp, Kp, Vp, Yp);

    gemm_out_tf32<<<dim3(C_EMB / BN, M_ROWS / BM), 256>>>(Yp, Wp, bp, out,
                                                          M_ROWS, C_EMB, C_EMB);
}

// round 6
// speedup vs baseline: 3.6226x; 1.0088x over previous
#include <cuda_runtime.h>
#include <cstdint>

#define T_SEQ   2048
#define NH      16
#define HD      64
#define C_EMB   1024
#define BATCH   4
#define M_ROWS  (BATCH * T_SEQ)   // 8192

// Scratch (allocation-free rule: __device__ globals)
__device__ float g_Q[(size_t)M_ROWS * C_EMB];
__device__ float g_K[(size_t)M_ROWS * C_EMB];
__device__ float g_V[(size_t)M_ROWS * C_EMB];
__device__ float g_Yatt[(size_t)M_ROWS * C_EMB];

__device__ __forceinline__ uint32_t f2tf32(float x) {
    uint32_t r;
    asm("cvt.rna.tf32.f32 %0, %1;" : "=r"(r) : "f"(x));
    return r;
}

__device__ __forceinline__ void mma_tf32(float* c, const uint32_t* a, const uint32_t* b) {
    asm volatile(
        "mma.sync.aligned.m16n8k8.row.col.f32.tf32.tf32.f32 "
        "{%0,%1,%2,%3}, {%4,%5,%6,%7}, {%8,%9}, {%0,%1,%2,%3};"
        : "+f"(c[0]), "+f"(c[1]), "+f"(c[2]), "+f"(c[3])
        : "r"(a[0]), "r"(a[1]), "r"(a[2]), "r"(a[3]), "r"(b[0]), "r"(b[1]));
}

// ---------------------------------------------------------------------------
// tf32 tensor-core GEMM body: C = A[M,K] @ B[K,N] + bias
// 128x128x16 tile, 8 warps, warp tile 64x32. Double-buffered smem,
// ONE __syncthreads per k-tile (end-of-iter barrier protects buffer reuse).
// MODE 0: row-major [M,N].  MODE 1: QKV scatter to [B,H,T,D].
// ---------------------------------------------------------------------------
#define BM 128
#define BN 128
#define BK 16
#define LDST 136   // BM + 8 pad

template <int MODE>
__device__ __forceinline__ void gemm_body(
    const float* __restrict__ A, const float* __restrict__ B,
    const float* __restrict__ bias, float* __restrict__ Cout,
    int M, int N, int K)
{
    __shared__ uint32_t SA[2][BK][LDST];
    __shared__ uint32_t SB[2][BK][LDST];

    const int tid  = threadIdx.x;
    const int bm   = blockIdx.y * BM;
    const int bn   = blockIdx.x * BN;
    const int wid  = tid >> 5;
    const int lane = tid & 31;
    const int g    = lane >> 2;
    const int tig  = lane & 3;
    const int wm   = (wid & 1) * 64;
    const int wn   = (wid >> 1) * 32;

    const int a_m0 = tid >> 2;              const int a_k0 = (tid & 3) << 2;
    const int a_m1 = (tid + 256) >> 2;      const int a_k1 = ((tid + 256) & 3) << 2;
    const int b_k0 = tid >> 5;              const int b_n0 = (tid & 31) << 2;
    const int b_k1 = (tid + 256) >> 5;      const int b_n1 = ((tid + 256) & 31) << 2;

    const float* Ap0 = A + (size_t)(bm + a_m0) * K + a_k0;
    const float* Ap1 = A + (size_t)(bm + a_m1) * K + a_k1;
    const float* Bp0 = B + (size_t)b_k0 * N + bn + b_n0;
    const float* Bp1 = B + (size_t)b_k1 * N + bn + b_n1;

    float4 av0 = *(const float4*)Ap0;
    float4 av1 = *(const float4*)Ap1;
    float4 bv0 = *(const float4*)Bp0;
    float4 bv1 = *(const float4*)Bp1;

    float acc[4][4][4];
#pragma unroll
    for (int i = 0; i < 4; i++)
#pragma unroll
        for (int j = 0; j < 4; j++)
#pragma unroll
            for (int r = 0; r < 4; r++) acc[i][j][r] = 0.f;

#define STORE_TILE(bf)                                                        \
    do {                                                                      \
        SA[bf][a_k0 + 0][a_m0] = f2tf32(av0.x);                               \
        SA[bf][a_k0 + 1][a_m0] = f2tf32(av0.y);                               \
        SA[bf][a_k0 + 2][a_m0] = f2tf32(av0.z);                               \
        SA[bf][a_k0 + 3][a_m0] = f2tf32(av0.w);                               \
        SA[bf][a_k1 + 0][a_m1] = f2tf32(av1.x);                               \
        SA[bf][a_k1 + 1][a_m1] = f2tf32(av1.y);                               \
        SA[bf][a_k1 + 2][a_m1] = f2tf32(av1.z);                               \
        SA[bf][a_k1 + 3][a_m1] = f2tf32(av1.w);                               \
        *(uint4*)&SB[bf][b_k0][b_n0] =                                        \
            make_uint4(f2tf32(bv0.x), f2tf32(bv0.y), f2tf32(bv0.z), f2tf32(bv0.w)); \
        *(uint4*)&SB[bf][b_k1][b_n1] =                                        \
            make_uint4(f2tf32(bv1.x), f2tf32(bv1.y), f2tf32(bv1.z), f2tf32(bv1.w)); \
    } while (0)

    STORE_TILE(0);
    __syncthreads();

    int buf = 0;
    for (int k0 = 0; k0 < K; k0 += BK, buf ^= 1) {
        const bool has_next = (k0 + BK < K);
        if (has_next) {
            Ap0 += BK; Ap1 += BK;
            Bp0 += (size_t)BK * N; Bp1 += (size_t)BK * N;
            av0 = *(const float4*)Ap0;
            av1 = *(const float4*)Ap1;
            bv0 = *(const float4*)Bp0;
            bv1 = *(const float4*)Bp1;
        }

#pragma unroll
        for (int ks = 0; ks < BK; ks += 8) {
            uint32_t af[4][4], bfr[4][2];
#pragma unroll
            for (int i = 0; i < 4; i++) {
                const int mb = wm + 16 * i;
                af[i][0] = SA[buf][ks + tig][mb + g];
                af[i][1] = SA[buf][ks + tig][mb + g + 8];
                af[i][2] = SA[buf][ks + tig + 4][mb + g];
                af[i][3] = SA[buf][ks + tig + 4][mb + g + 8];
            }
#pragma unroll
            for (int j = 0; j < 4; j++) {
                const int nb = wn + 8 * j;
                bfr[j][0] = SB[buf][ks + tig][nb + g];
                bfr[j][1] = SB[buf][ks + tig + 4][nb + g];
            }
#pragma unroll
            for (int i = 0; i < 4; i++)
#pragma unroll
                for (int j = 0; j < 4; j++)
                    mma_tf32(acc[i][j], af[i], bfr[j]);
        }

        if (has_next) STORE_TILE(buf ^ 1);
        __syncthreads();
    }
#undef STORE_TILE

#pragma unroll
    for (int j = 0; j < 4; j++) {
        const int col = bn + wn + 8 * j + 2 * tig;
        const float b0 = bias[col];
        const float b1 = bias[col + 1];
#pragma unroll
        for (int i = 0; i < 4; i++) {
            const int row = bm + wm + 16 * i + g;
            const float2 v0 = make_float2(acc[i][j][0] + b0, acc[i][j][1] + b1);
            const float2 v1 = make_float2(acc[i][j][2] + b0, acc[i][j][3] + b1);
            if (MODE == 0) {
                *(float2*)&Cout[(size_t)row * N + col] = v0;
                *(float2*)&Cout[(size_t)(row + 8) * N + col] = v1;
            } else {
                const int h_ = col >> 6;
                const int d_ = col & (HD - 1);
                const int b0_ = row >> 11;
                const int t0_ = row & (T_SEQ - 1);
                const int b1_ = (row + 8) >> 11;
                const int t1_ = (row + 8) & (T_SEQ - 1);
                *(float2*)&Cout[(((size_t)b0_ * NH + h_) * T_SEQ + t0_) * HD + d_] = v0;
                *(float2*)&Cout[(((size_t)b1_ * NH + h_) * T_SEQ + t1_) * HD + d_] = v1;
            }
        }
    }
}

// Fused QKV projection: blockIdx.z selects (W, bias, out). One tail wave.
__global__ __launch_bounds__(256) void gemm_qkv_tf32(
    const float* __restrict__ A,
    const float* __restrict__ W0, const float* __restrict__ W1, const float* __restrict__ W2,
    const float* __restrict__ c0, const float* __restrict__ c1, const float* __restrict__ c2,
    float* __restrict__ O0, float* __restrict__ O1, float* __restrict__ O2,
    int M, int N, int K)
{
    const int z = blockIdx.z;
    const float* B    = (z == 0) ? W0 : (z == 1) ? W1 : W2;
    const float* bias = (z == 0) ? c0 : (z == 1) ? c1 : c2;
    float* Cout       = (z == 0) ? O0 : (z == 1) ? O1 : O2;
    gemm_body<1>(A, B, bias, Cout, M, N, K);
}

__global__ __launch_bounds__(256) void gemm_out_tf32(
    const float* __restrict__ A, const float* __restrict__ B,
    const float* __restrict__ bias, float* __restrict__ Cout,
    int M, int N, int K)
{
    gemm_body<0>(A, B, bias, Cout, M, N, K);
}

// ---------------------------------------------------------------------------
// Tensor-core flash attention (tf32 mma, fp32 softmax/accum, causal).
// 128 queries/CTA, 64-key tiles, 8 warps x 16 query rows each.
// Q fragments reloaded from smem per k-step (saves 32 regs -> 2 CTAs/SM).
// ---------------------------------------------------------------------------
#define QS_STRIDE 68
#define KS_STRIDE 68
#define VS_STRIDE 72
#define ATTN_SMEM ((128 * QS_STRIDE + 64 * KS_STRIDE + 64 * VS_STRIDE) * 4)  // 70656 B

__global__ __launch_bounds__(256, 2) void attn_tc_kernel(
    const float* __restrict__ Q, const float* __restrict__ K,
    const float* __restrict__ V, float* __restrict__ Y)
{
    extern __shared__ uint32_t smu[];
    uint32_t* Qsm = smu;                          // [128][68] tf32 (pre-scaled)
    uint32_t* Ksm = smu + 128 * QS_STRIDE;        // [64][68]
    uint32_t* Vsm = Ksm + 64 * KS_STRIDE;         // [64][72]

    const int tid  = threadIdx.x;
    const int w    = tid >> 5;
    const int lane = tid & 31;
    const int g    = lane >> 2;
    const int tig  = lane & 3;
    const int bh   = blockIdx.y;
    const int qb   = blockIdx.x;
    const int q0   = qb * 128;

    const float* Qg = Q + ((size_t)bh * T_SEQ + q0) * HD;
    const float* Kg = K + (size_t)bh * T_SEQ * HD;
    const float* Vg = V + (size_t)bh * T_SEQ * HD;

    // Stage Q tile (scaled by 1/sqrt(D)=0.125, tf32)
#pragma unroll
    for (int r = 0; r < 8; r++) {
        const int idx = tid + r * 256;
        const int row = idx >> 4;
        const int d4  = (idx & 15) << 2;
        const float4 v = *(const float4*)(Qg + row * HD + d4);
        uint32_t* p = &Qsm[row * QS_STRIDE + d4];
        p[0] = f2tf32(v.x * 0.125f);
        p[1] = f2tf32(v.y * 0.125f);
        p[2] = f2tf32(v.z * 0.125f);
        p[3] = f2tf32(v.w * 0.125f);
    }

    float o[8][4];
#pragma unroll
    for (int j = 0; j < 8; j++)
#pragma unroll
        for (int r = 0; r < 4; r++) o[j][r] = 0.f;
    float m_lo = -1e30f, m_hi = -1e30f, l_lo = 0.f, l_hi = 0.f;

    const int r0      = 16 * w + g;       // warp-local row (lo)
    const int row_lo  = q0 + r0;
    const int row_hi  = row_lo + 8;
    const int row_max_w = q0 + 16 * w + 15;
    const int qbase = lane & 28;
    const int srcA  = qbase + (tig >> 1);
    const int srcB  = srcA + 2;

    for (int s0 = 0; s0 < q0 + 128; s0 += 64) {
        __syncthreads();   // also orders initial Q staging before first use
        // Load K,V tiles (64x64 each), tf32
#pragma unroll
        for (int r = 0; r < 4; r++) {
            const int idx = tid + r * 256;
            const int row = idx >> 4;
            const int d4  = (idx & 15) << 2;
            const float4 kv = *(const float4*)(Kg + (size_t)(s0 + row) * HD + d4);
            uint32_t* pk = &Ksm[row * KS_STRIDE + d4];
            pk[0] = f2tf32(kv.x); pk[1] = f2tf32(kv.y);
            pk[2] = f2tf32(kv.z); pk[3] = f2tf32(kv.w);
            const float4 vv = *(const float4*)(Vg + (size_t)(s0 + row) * HD + d4);
            uint32_t* pv = &Vsm[row * VS_STRIDE + d4];
            pv[0] = f2tf32(vv.x); pv[1] = f2tf32(vv.y);
            pv[2] = f2tf32(vv.z); pv[3] = f2tf32(vv.w);
        }
        __syncthreads();

        if (s0 > row_max_w) continue;  // fully masked for this warp's rows

        // S = Q @ K^T : Q fragments loaded from smem per k-step
        float s_[8][4];
#pragma unroll
        for (int j = 0; j < 8; j++)
#pragma unroll
            for (int r = 0; r < 4; r++) s_[j][r] = 0.f;

#pragma unroll
        for (int ks = 0; ks < 8; ks++) {
            uint32_t a[4];
            a[0] = Qsm[r0 * QS_STRIDE + 8 * ks + tig];
            a[1] = Qsm[(r0 + 8) * QS_STRIDE + 8 * ks + tig];
            a[2] = Qsm[r0 * QS_STRIDE + 8 * ks + tig + 4];
            a[3] = Qsm[(r0 + 8) * QS_STRIDE + 8 * ks + tig + 4];
#pragma unroll
            for (int j = 0; j < 8; j++) {
                uint32_t b[2];
                b[0] = Ksm[(8 * j + g) * KS_STRIDE + 8 * ks + tig];
                b[1] = Ksm[(8 * j + g) * KS_STRIDE + 8 * ks + tig + 4];
                mma_tf32(s_[j], a, b);
            }
        }

        // causal mask (only tiles intersecting the diagonal for this warp)
        if (s0 + 63 > q0 + 16 * w) {
#pragma unroll
            for (int j = 0; j < 8; j++) {
                const int c0 = s0 + 8 * j + 2 * tig;
                if (c0 > row_lo)     s_[j][0] = -1e30f;
                if (c0 + 1 > row_lo) s_[j][1] = -1e30f;
                if (c0 > row_hi)     s_[j][2] = -1e30f;
                if (c0 + 1 > row_hi) s_[j][3] = -1e30f;
            }
        }

        // online softmax (rows g and g+8, reduced across the quad)
        float t_lo = -1e30f, t_hi = -1e30f;
#pragma unroll
        for (int j = 0; j < 8; j++) {
            t_lo = fmaxf(t_lo, fmaxf(s_[j][0], s_[j][1]));
            t_hi = fmaxf(t_hi, fmaxf(s_[j][2], s_[j][3]));
        }
        t_lo = fmaxf(t_lo, __shfl_xor_sync(0xffffffffu, t_lo, 1));
        t_lo = fmaxf(t_lo, __shfl_xor_sync(0xffffffffu, t_lo, 2));
        t_hi = fmaxf(t_hi, __shfl_xor_sync(0xffffffffu, t_hi, 1));
        t_hi = fmaxf(t_hi, __shfl_xor_sync(0xffffffffu, t_hi, 2));

        const float mn_lo = fmaxf(m_lo, t_lo);
        const float mn_hi = fmaxf(m_hi, t_hi);
        const float a_lo = __expf(m_lo - mn_lo);
        const float a_hi = __expf(m_hi - mn_hi);
        m_lo = mn_lo; m_hi = mn_hi;

        float rs_lo = 0.f, rs_hi = 0.f;
#pragma unroll
        for (int j = 0; j < 8; j++) {
            const float p0 = __expf(s_[j][0] - mn_lo);
            const float p1 = __expf(s_[j][1] - mn_lo);
            const float p2 = __expf(s_[j][2] - mn_hi);
            const float p3 = __expf(s_[j][3] - mn_hi);
            rs_lo += p0 + p1;
            rs_hi += p2 + p3;
            s_[j][0] = __uint_as_float(f2tf32(p0));
            s_[j][1] = __uint_as_float(f2tf32(p1));
            s_[j][2] = __uint_as_float(f2tf32(p2));
            s_[j][3] = __uint_as_float(f2tf32(p3));
        }
        rs_lo += __shfl_xor_sync(0xffffffffu, rs_lo, 1);
        rs_lo += __shfl_xor_sync(0xffffffffu, rs_lo, 2);
        rs_hi += __shfl_xor_sync(0xffffffffu, rs_hi, 1);
        rs_hi += __shfl_xor_sync(0xffffffffu, rs_hi, 2);
        l_lo = l_lo * a_lo + rs_lo;
        l_hi = l_hi * a_hi + rs_hi;

#pragma unroll
        for (int jd = 0; jd < 8; jd++) {
            o[jd][0] *= a_lo; o[jd][1] *= a_lo;
            o[jd][2] *= a_hi; o[jd][3] *= a_hi;
        }

        // O += P @ V : permute P C-frag -> A-frag via quad shuffles
#pragma unroll
        for (int ks = 0; ks < 8; ks++) {
            const float p0 = s_[ks][0], p1 = s_[ks][1];
            const float p2 = s_[ks][2], p3 = s_[ks][3];
            const float u0 = __shfl_sync(0xffffffffu, p0, srcA);
            const float u1 = __shfl_sync(0xffffffffu, p1, srcA);
            const float v0 = __shfl_sync(0xffffffffu, p2, srcA);
            const float v1 = __shfl_sync(0xffffffffu, p3, srcA);
            const float x0 = __shfl_sync(0xffffffffu, p0, srcB);
            const float x1 = __shfl_sync(0xffffffffu, p1, srcB);
            const float y0 = __shfl_sync(0xffffffffu, p2, srcB);
            const float y1 = __shfl_sync(0xffffffffu, p3, srcB);
            uint32_t a[4];
            a[0] = __float_as_uint((tig & 1) ? u1 : u0);
            a[1] = __float_as_uint((tig & 1) ? v1 : v0);
            a[2] = __float_as_uint((tig & 1) ? x1 : x0);
            a[3] = __float_as_uint((tig & 1) ? y1 : y0);
#pragma unroll
            for (int jd = 0; jd < 8; jd++) {
                uint32_t b[2];
                b[0] = Vsm[(8 * ks + tig) * VS_STRIDE + 8 * jd + g];
                b[1] = Vsm[(8 * ks + tig + 4) * VS_STRIDE + 8 * jd + g];
                mma_tf32(o[jd], a, b);
            }
        }
    }

    // Normalize + write Y in [B,T,C] layout
    const float il_lo = 1.0f / l_lo;
    const float il_hi = 1.0f / l_hi;
    const int b_ = bh >> 4;
    const int h_ = bh & 15;
    float* Yb = Y + (size_t)b_ * T_SEQ * C_EMB + h_ * HD;
#pragma unroll
    for (int jd = 0; jd < 8; jd++) {
        const int d = 8 * jd + 2 * tig;
        const float2 vlo = make_float2(o[jd][0] * il_lo, o[jd][1] * il_lo);
        const float2 vhi = make_float2(o[jd][2] * il_hi, o[jd][3] * il_hi);
        *(float2*)&Yb[(size_t)row_lo * C_EMB + d] = vlo;
        *(float2*)&Yb[(size_t)row_hi * C_EMB + d] = vhi;
    }
}

// ---------------------------------------------------------------------------
extern "C" void kernel_launch(void* const* d_in, const int* in_sizes, int n_in,
                              void* d_out, int out_size)
{
    const float* x  = (const float*)d_in[0];
    const float* Wq = (const float*)d_in[1];
    const float* bq = (const float*)d_in[2];
    const float* Wk = (const float*)d_in[3];
    const float* bk = (const float*)d_in[4];
    const float* Wv = (const float*)d_in[5];
    const float* bv = (const float*)d_in[6];
    const float* Wp = (const float*)d_in[7];
    const float* bp = (const float*)d_in[8];
    float* out = (float*)d_out;

    float *Qp, *Kp, *Vp, *Yp;
    cudaGetSymbolAddress((void**)&Qp, g_Q);
    cudaGetSymbolAddress((void**)&Kp, g_K);
    cudaGetSymbolAddress((void**)&Vp, g_V);
    cudaGetSymbolAddress((void**)&Yp, g_Yatt);

    cudaFuncSetAttribute(attn_tc_kernel,
                         cudaFuncAttributeMaxDynamicSharedMemorySize, ATTN_SMEM);

    const dim3 gqkv(C_EMB / BN, M_ROWS / BM, 3);  // (8, 64, 3)
    gemm_qkv_tf32<<<gqkv, 256>>>(x, Wq, Wk, Wv, bq, bk, bv, Qp, Kp, Vp,
                                 M_ROWS, C_EMB, C_EMB);

    attn_tc_kernel<<<dim3(T_SEQ / 128, BATCH * NH), 256, ATTN_SMEM>>>(Qp, Kp, Vp, Yp);

    gemm_out_tf32<<<dim3(C_EMB / BN, M_ROWS / BM), 256>>>(Yp, Wp, bp, out,
                                                          M_ROWS, C_EMB, C_EMB);
}

// round 7
// speedup vs baseline: 3.9713x; 1.0962x over previous
#include <cuda_runtime.h>
#include <cstdint>

#define T_SEQ   2048
#define NH      16
#define HD      64
#define C_EMB   1024
#define BATCH   4
#define M_ROWS  (BATCH * T_SEQ)   // 8192

// Scratch (allocation-free rule: __device__ globals)
__device__ float g_Q[(size_t)M_ROWS * C_EMB];
__device__ float g_K[(size_t)M_ROWS * C_EMB];
__device__ float g_V[(size_t)M_ROWS * C_EMB];
__device__ float g_Yatt[(size_t)M_ROWS * C_EMB];

__device__ __forceinline__ uint32_t f2tf32(float x) {
    uint32_t r;
    asm("cvt.rna.tf32.f32 %0, %1;" : "=r"(r) : "f"(x));
    return r;
}

__device__ __forceinline__ void mma_tf32(float* c, const uint32_t* a, const uint32_t* b) {
    asm volatile(
        "mma.sync.aligned.m16n8k8.row.col.f32.tf32.tf32.f32 "
        "{%0,%1,%2,%3}, {%4,%5,%6,%7}, {%8,%9}, {%0,%1,%2,%3};"
        : "+f"(c[0]), "+f"(c[1]), "+f"(c[2]), "+f"(c[3])
        : "r"(a[0]), "r"(a[1]), "r"(a[2]), "r"(a[3]), "r"(b[0]), "r"(b[1]));
}

__device__ __forceinline__ void ldsm_x4(uint32_t* r, uint32_t addr) {
    asm volatile(
        "ldmatrix.sync.aligned.m8n8.x4.shared.b16 {%0,%1,%2,%3}, [%4];"
        : "=r"(r[0]), "=r"(r[1]), "=r"(r[2]), "=r"(r[3]) : "r"(addr));
}

// ---------------------------------------------------------------------------
// tf32 tensor-core GEMM body: C = A[M,K] @ B[K,N] + bias
// 128x128x16 tile, 8 warps, warp tile 64x32. Double-buffered smem, one
// __syncthreads per k-tile. A fragments via ldmatrix.x4 (A smem [m][k],
// stride 20 words -> conflict-free LDSM rows). B scalar from [k][n].
// MODE 0: row-major [M,N].  MODE 1: QKV scatter to [B,H,T,D].
// ---------------------------------------------------------------------------
#define BM 128
#define BN 128
#define BK 16
#define ASTRIDE 20   // words per A row (16 k + 4 pad) -> LDSM conflict-free
#define LDSTB 136    // BN + 8 pad for B [k][n]

template <int MODE>
__device__ __forceinline__ void gemm_body(
    const float* __restrict__ A, const float* __restrict__ B,
    const float* __restrict__ bias, float* __restrict__ Cout,
    int M, int N, int K)
{
    __shared__ uint32_t SA[2][BM * ASTRIDE];   // [m][k] tf32
    __shared__ uint32_t SB[2][BK][LDSTB];      // [k][n] tf32

    const int tid  = threadIdx.x;
    const int bm   = blockIdx.y * BM;
    const int bn   = blockIdx.x * BN;
    const int wid  = tid >> 5;
    const int lane = tid & 31;
    const int g    = lane >> 2;
    const int tig  = lane & 3;
    const int wm   = (wid & 1) * 64;
    const int wn   = (wid >> 1) * 32;

    // A staging: row a_m0 (+64), k-quad a_k0
    const int a_m0 = tid >> 2;              const int a_k0 = (tid & 3) << 2;
    const int b_k0 = tid >> 5;              const int b_n0 = (tid & 31) << 2;
    const int b_k1 = (tid + 256) >> 5;      const int b_n1 = ((tid + 256) & 31) << 2;

    const float* Ap0 = A + (size_t)(bm + a_m0) * K + a_k0;
    const float* Ap1 = A + (size_t)(bm + a_m0 + 64) * K + a_k0;
    const float* Bp0 = B + (size_t)b_k0 * N + bn + b_n0;
    const float* Bp1 = B + (size_t)b_k1 * N + bn + b_n1;

    float4 av0 = *(const float4*)Ap0;
    float4 av1 = *(const float4*)Ap1;
    float4 bv0 = *(const float4*)Bp0;
    float4 bv1 = *(const float4*)Bp1;

    // ldmatrix lane address part: row (lane&15), col-block ((lane>>4)*4)
    const uint32_t sa_base0 = (uint32_t)__cvta_generic_to_shared(&SA[0][0]);
    const uint32_t sa_base1 = (uint32_t)__cvta_generic_to_shared(&SA[1][0]);
    const uint32_t a_lane_off = (((lane & 15) * ASTRIDE) + ((lane >> 4) << 2)) * 4;

    float acc[4][4][4];
#pragma unroll
    for (int i = 0; i < 4; i++)
#pragma unroll
        for (int j = 0; j < 4; j++)
#pragma unroll
            for (int r = 0; r < 4; r++) acc[i][j][r] = 0.f;

#define STORE_TILE(bf)                                                        \
    do {                                                                      \
        *(uint4*)&SA[bf][a_m0 * ASTRIDE + a_k0] =                             \
            make_uint4(f2tf32(av0.x), f2tf32(av0.y), f2tf32(av0.z), f2tf32(av0.w)); \
        *(uint4*)&SA[bf][(a_m0 + 64) * ASTRIDE + a_k0] =                      \
            make_uint4(f2tf32(av1.x), f2tf32(av1.y), f2tf32(av1.z), f2tf32(av1.w)); \
        *(uint4*)&SB[bf][b_k0][b_n0] =                                        \
            make_uint4(f2tf32(bv0.x), f2tf32(bv0.y), f2tf32(bv0.z), f2tf32(bv0.w)); \
        *(uint4*)&SB[bf][b_k1][b_n1] =                                        \
            make_uint4(f2tf32(bv1.x), f2tf32(bv1.y), f2tf32(bv1.z), f2tf32(bv1.w)); \
    } while (0)

    STORE_TILE(0);
    __syncthreads();

    int buf = 0;
    for (int k0 = 0; k0 < K; k0 += BK, buf ^= 1) {
        const bool has_next = (k0 + BK < K);
        if (has_next) {
            Ap0 += BK; Ap1 += BK;
            Bp0 += (size_t)BK * N; Bp1 += (size_t)BK * N;
            av0 = *(const float4*)Ap0;
            av1 = *(const float4*)Ap1;
            bv0 = *(const float4*)Bp0;
            bv1 = *(const float4*)Bp1;
        }

        const uint32_t sa_base = buf ? sa_base1 : sa_base0;
#pragma unroll
        for (int ks = 0; ks < BK; ks += 8) {
            uint32_t af[4][4], bfr[4][2];
#pragma unroll
            for (int i = 0; i < 4; i++) {
                const uint32_t addr =
                    sa_base + a_lane_off + (uint32_t)(((wm + 16 * i) * ASTRIDE + ks) * 4);
                ldsm_x4(af[i], addr);
            }
#pragma unroll
            for (int j = 0; j < 4; j++) {
                const int nb = wn + 8 * j;
                bfr[j][0] = SB[buf][ks + tig][nb + g];
                bfr[j][1] = SB[buf][ks + tig + 4][nb + g];
            }
#pragma unroll
            for (int i = 0; i < 4; i++)
#pragma unroll
                for (int j = 0; j < 4; j++)
                    mma_tf32(acc[i][j], af[i], bfr[j]);
        }

        if (has_next) STORE_TILE(buf ^ 1);
        __syncthreads();
    }
#undef STORE_TILE

#pragma unroll
    for (int j = 0; j < 4; j++) {
        const int col = bn + wn + 8 * j + 2 * tig;
        const float b0 = bias[col];
        const float b1 = bias[col + 1];
#pragma unroll
        for (int i = 0; i < 4; i++) {
            const int row = bm + wm + 16 * i + g;
            const float2 v0 = make_float2(acc[i][j][0] + b0, acc[i][j][1] + b1);
            const float2 v1 = make_float2(acc[i][j][2] + b0, acc[i][j][3] + b1);
            if (MODE == 0) {
                *(float2*)&Cout[(size_t)row * N + col] = v0;
                *(float2*)&Cout[(size_t)(row + 8) * N + col] = v1;
            } else {
                const int h_ = col >> 6;
                const int d_ = col & (HD - 1);
                const int b0_ = row >> 11;
                const int t0_ = row & (T_SEQ - 1);
                const int b1_ = (row + 8) >> 11;
                const int t1_ = (row + 8) & (T_SEQ - 1);
                *(float2*)&Cout[(((size_t)b0_ * NH + h_) * T_SEQ + t0_) * HD + d_] = v0;
                *(float2*)&Cout[(((size_t)b1_ * NH + h_) * T_SEQ + t1_) * HD + d_] = v1;
            }
        }
    }
}

// Fused QKV projection: blockIdx.z selects (W, bias, out). One tail wave.
__global__ __launch_bounds__(256) void gemm_qkv_tf32(
    const float* __restrict__ A,
    const float* __restrict__ W0, const float* __restrict__ W1, const float* __restrict__ W2,
    const float* __restrict__ c0, const float* __restrict__ c1, const float* __restrict__ c2,
    float* __restrict__ O0, float* __restrict__ O1, float* __restrict__ O2,
    int M, int N, int K)
{
    const int z = blockIdx.z;
    const float* B    = (z == 0) ? W0 : (z == 1) ? W1 : W2;
    const float* bias = (z == 0) ? c0 : (z == 1) ? c1 : c2;
    float* Cout       = (z == 0) ? O0 : (z == 1) ? O1 : O2;
    gemm_body<1>(A, B, bias, Cout, M, N, K);
}

__global__ __launch_bounds__(256) void gemm_out_tf32(
    const float* __restrict__ A, const float* __restrict__ B,
    const float* __restrict__ bias, float* __restrict__ Cout,
    int M, int N, int K)
{
    gemm_body<0>(A, B, bias, Cout, M, N, K);
}

// ---------------------------------------------------------------------------
// Tensor-core flash attention (tf32 mma, fp32 softmax/accum, causal).
// 128 queries/CTA, 64-key tiles, 8 warps x 16 query rows each.  (unchanged)
// ---------------------------------------------------------------------------
#define QS_STRIDE 68
#define KS_STRIDE 68
#define VS_STRIDE 72
#define ATTN_SMEM ((128 * QS_STRIDE + 64 * KS_STRIDE + 64 * VS_STRIDE) * 4)  // 70656 B

__global__ __launch_bounds__(256, 2) void attn_tc_kernel(
    const float* __restrict__ Q, const float* __restrict__ K,
    const float* __restrict__ V, float* __restrict__ Y)
{
    extern __shared__ uint32_t smu[];
    uint32_t* Qsm = smu;                          // [128][68] tf32 (pre-scaled)
    uint32_t* Ksm = smu + 128 * QS_STRIDE;        // [64][68]
    uint32_t* Vsm = Ksm + 64 * KS_STRIDE;         // [64][72]

    const int tid  = threadIdx.x;
    const int w    = tid >> 5;
    const int lane = tid & 31;
    const int g    = lane >> 2;
    const int tig  = lane & 3;
    const int bh   = blockIdx.y;
    const int qb   = blockIdx.x;
    const int q0   = qb * 128;

    const float* Qg = Q + ((size_t)bh * T_SEQ + q0) * HD;
    const float* Kg = K + (size_t)bh * T_SEQ * HD;
    const float* Vg = V + (size_t)bh * T_SEQ * HD;

#pragma unroll
    for (int r = 0; r < 8; r++) {
        const int idx = tid + r * 256;
        const int row = idx >> 4;
        const int d4  = (idx & 15) << 2;
        const float4 v = *(const float4*)(Qg + row * HD + d4);
        uint32_t* p = &Qsm[row * QS_STRIDE + d4];
        p[0] = f2tf32(v.x * 0.125f);
        p[1] = f2tf32(v.y * 0.125f);
        p[2] = f2tf32(v.z * 0.125f);
        p[3] = f2tf32(v.w * 0.125f);
    }

    float o[8][4];
#pragma unroll
    for (int j = 0; j < 8; j++)
#pragma unroll
        for (int r = 0; r < 4; r++) o[j][r] = 0.f;
    float m_lo = -1e30f, m_hi = -1e30f, l_lo = 0.f, l_hi = 0.f;

    const int r0      = 16 * w + g;
    const int row_lo  = q0 + r0;
    const int row_hi  = row_lo + 8;
    const int row_max_w = q0 + 16 * w + 15;
    const int qbase = lane & 28;
    const int srcA  = qbase + (tig >> 1);
    const int srcB  = srcA + 2;

    for (int s0 = 0; s0 < q0 + 128; s0 += 64) {
        __syncthreads();
#pragma unroll
        for (int r = 0; r < 4; r++) {
            const int idx = tid + r * 256;
            const int row = idx >> 4;
            const int d4  = (idx & 15) << 2;
            const float4 kv = *(const float4*)(Kg + (size_t)(s0 + row) * HD + d4);
            uint32_t* pk = &Ksm[row * KS_STRIDE + d4];
            pk[0] = f2tf32(kv.x); pk[1] = f2tf32(kv.y);
            pk[2] = f2tf32(kv.z); pk[3] = f2tf32(kv.w);
            const float4 vv = *(const float4*)(Vg + (size_t)(s0 + row) * HD + d4);
            uint32_t* pv = &Vsm[row * VS_STRIDE + d4];
            pv[0] = f2tf32(vv.x); pv[1] = f2tf32(vv.y);
            pv[2] = f2tf32(vv.z); pv[3] = f2tf32(vv.w);
        }
        __syncthreads();

        if (s0 > row_max_w) continue;

        float s_[8][4];
#pragma unroll
        for (int j = 0; j < 8; j++)
#pragma unroll
            for (int r = 0; r < 4; r++) s_[j][r] = 0.f;

#pragma unroll
        for (int ks = 0; ks < 8; ks++) {
            uint32_t a[4];
            a[0] = Qsm[r0 * QS_STRIDE + 8 * ks + tig];
            a[1] = Qsm[(r0 + 8) * QS_STRIDE + 8 * ks + tig];
            a[2] = Qsm[r0 * QS_STRIDE + 8 * ks + tig + 4];
            a[3] = Qsm[(r0 + 8) * QS_STRIDE + 8 * ks + tig + 4];
#pragma unroll
            for (int j = 0; j < 8; j++) {
                uint32_t b[2];
                b[0] = Ksm[(8 * j + g) * KS_STRIDE + 8 * ks + tig];
                b[1] = Ksm[(8 * j + g) * KS_STRIDE + 8 * ks + tig + 4];
                mma_tf32(s_[j], a, b);
            }
        }

        if (s0 + 63 > q0 + 16 * w) {
#pragma unroll
            for (int j = 0; j < 8; j++) {
                const int c0 = s0 + 8 * j + 2 * tig;
                if (c0 > row_lo)     s_[j][0] = -1e30f;
                if (c0 + 1 > row_lo) s_[j][1] = -1e30f;
                if (c0 > row_hi)     s_[j][2] = -1e30f;
                if (c0 + 1 > row_hi) s_[j][3] = -1e30f;
            }
        }

        float t_lo = -1e30f, t_hi = -1e30f;
#pragma unroll
        for (int j = 0; j < 8; j++) {
            t_lo = fmaxf(t_lo, fmaxf(s_[j][0], s_[j][1]));
            t_hi = fmaxf(t_hi, fmaxf(s_[j][2], s_[j][3]));
        }
        t_lo = fmaxf(t_lo, __shfl_xor_sync(0xffffffffu, t_lo, 1));
        t_lo = fmaxf(t_lo, __shfl_xor_sync(0xffffffffu, t_lo, 2));
        t_hi = fmaxf(t_hi, __shfl_xor_sync(0xffffffffu, t_hi, 1));
        t_hi = fmaxf(t_hi, __shfl_xor_sync(0xffffffffu, t_hi, 2));

        const float mn_lo = fmaxf(m_lo, t_lo);
        const float mn_hi = fmaxf(m_hi, t_hi);
        const float a_lo = __expf(m_lo - mn_lo);
        const float a_hi = __expf(m_hi - mn_hi);
        m_lo = mn_lo; m_hi = mn_hi;

        float rs_lo = 0.f, rs_hi = 0.f;
#pragma unroll
        for (int j = 0; j < 8; j++) {
            const float p0 = __expf(s_[j][0] - mn_lo);
            const float p1 = __expf(s_[j][1] - mn_lo);
            const float p2 = __expf(s_[j][2] - mn_hi);
            const float p3 = __expf(s_[j][3] - mn_hi);
            rs_lo += p0 + p1;
            rs_hi += p2 + p3;
            s_[j][0] = __uint_as_float(f2tf32(p0));
            s_[j][1] = __uint_as_float(f2tf32(p1));
            s_[j][2] = __uint_as_float(f2tf32(p2));
            s_[j][3] = __uint_as_float(f2tf32(p3));
        }
        rs_lo += __shfl_xor_sync(0xffffffffu, rs_lo, 1);
        rs_lo += __shfl_xor_sync(0xffffffffu, rs_lo, 2);
        rs_hi += __shfl_xor_sync(0xffffffffu, rs_hi, 1);
        rs_hi += __shfl_xor_sync(0xffffffffu, rs_hi, 2);
        l_lo = l_lo * a_lo + rs_lo;
        l_hi = l_hi * a_hi + rs_hi;

#pragma unroll
        for (int jd = 0; jd < 8; jd++) {
            o[jd][0] *= a_lo; o[jd][1] *= a_lo;
            o[jd][2] *= a_hi; o[jd][3] *= a_hi;
        }

#pragma unroll
        for (int ks = 0; ks < 8; ks++) {
            const float p0 = s_[ks][0], p1 = s_[ks][1];
            const float p2 = s_[ks][2], p3 = s_[ks][3];
            const float u0 = __shfl_sync(0xffffffffu, p0, srcA);
            const float u1 = __shfl_sync(0xffffffffu, p1, srcA);
            const float v0 = __shfl_sync(0xffffffffu, p2, srcA);
            const float v1 = __shfl_sync(0xffffffffu, p3, srcA);
            const float x0 = __shfl_sync(0xffffffffu, p0, srcB);
            const float x1 = __shfl_sync(0xffffffffu, p1, srcB);
            const float y0 = __shfl_sync(0xffffffffu, p2, srcB);
            const float y1 = __shfl_sync(0xffffffffu, p3, srcB);
            uint32_t a[4];
            a[0] = __float_as_uint((tig & 1) ? u1 : u0);
            a[1] = __float_as_uint((tig & 1) ? v1 : v0);
            a[2] = __float_as_uint((tig & 1) ? x1 : x0);
            a[3] = __float_as_uint((tig & 1) ? y1 : y0);
#pragma unroll
            for (int jd = 0; jd < 8; jd++) {
                uint32_t b[2];
                b[0] = Vsm[(8 * ks + tig) * VS_STRIDE + 8 * jd + g];
                b[1] = Vsm[(8 * ks + tig + 4) * VS_STRIDE + 8 * jd + g];
                mma_tf32(o[jd], a, b);
            }
        }
    }

    const float il_lo = 1.0f / l_lo;
    const float il_hi = 1.0f / l_hi;
    const int b_ = bh >> 4;
    const int h_ = bh & 15;
    float* Yb = Y + (size_t)b_ * T_SEQ * C_EMB + h_ * HD;
#pragma unroll
    for (int jd = 0; jd < 8; jd++) {
        const int d = 8 * jd + 2 * tig;
        const float2 vlo = make_float2(o[jd][0] * il_lo, o[jd][1] * il_lo);
        const float2 vhi = make_float2(o[jd][2] * il_hi, o[jd][3] * il_hi);
        *(float2*)&Yb[(size_t)row_lo * C_EMB + d] = vlo;
        *(float2*)&Yb[(size_t)row_hi * C_EMB + d] = vhi;
    }
}

// ---------------------------------------------------------------------------
extern "C" void kernel_launch(void* const* d_in, const int* in_sizes, int n_in,
                              void* d_out, int out_size)
{
    const float* x  = (const float*)d_in[0];
    const float* Wq = (const float*)d_in[1];
    const float* bq = (const float*)d_in[2];
    const float* Wk = (const float*)d_in[3];
    const float* bk = (const float*)d_in[4];
    const float* Wv = (const float*)d_in[5];
    const float* bv = (const float*)d_in[6];
    const float* Wp = (const float*)d_in[7];
    const float* bp = (const float*)d_in[8];
    float* out = (float*)d_out;

    float *Qp, *Kp, *Vp, *Yp;
    cudaGetSymbolAddress((void**)&Qp, g_Q);
    cudaGetSymbolAddress((void**)&Kp, g_K);
    cudaGetSymbolAddress((void**)&Vp, g_V);
    cudaGetSymbolAddress((void**)&Yp, g_Yatt);

    cudaFuncSetAttribute(attn_tc_kernel,
                         cudaFuncAttributeMaxDynamicSharedMemorySize, ATTN_SMEM);

    const dim3 gqkv(C_EMB / BN, M_ROWS / BM, 3);  // (8, 64, 3)
    gemm_qkv_tf32<<<gqkv, 256>>>(x, Wq, Wk, Wv, bq, bk, bv, Qp, Kp, Vp,
                                 M_ROWS, C_EMB, C_EMB);

    attn_tc_kernel<<<dim3(T_SEQ / 128, BATCH * NH), 256, ATTN_SMEM>>>(Qp, Kp, Vp, Yp);

    gemm_out_tf32<<<dim3(C_EMB / BN, M_ROWS / BM), 256>>>(Yp, Wp, bp, out,
                                                          M_ROWS, C_EMB, C_EMB);
}

// round 8
// speedup vs baseline: 3.9973x; 1.0066x over previous
#include <cuda_runtime.h>
#include <cstdint>

#define T_SEQ   2048
#define NH      16
#define HD      64
#define C_EMB   1024
#define BATCH   4
#define M_ROWS  (BATCH * T_SEQ)   // 8192

// Scratch (allocation-free rule: __device__ globals)
__device__ float g_Q[(size_t)M_ROWS * C_EMB];
__device__ float g_K[(size_t)M_ROWS * C_EMB];
__device__ float g_V[(size_t)M_ROWS * C_EMB];
__device__ float g_Yatt[(size_t)M_ROWS * C_EMB];

__device__ __forceinline__ uint32_t f2tf32(float x) {
    uint32_t r;
    asm("cvt.rna.tf32.f32 %0, %1;" : "=r"(r) : "f"(x));
    return r;
}

__device__ __forceinline__ void mma_tf32(float* c, const uint32_t* a, const uint32_t* b) {
    asm volatile(
        "mma.sync.aligned.m16n8k8.row.col.f32.tf32.tf32.f32 "
        "{%0,%1,%2,%3}, {%4,%5,%6,%7}, {%8,%9}, {%0,%1,%2,%3};"
        : "+f"(c[0]), "+f"(c[1]), "+f"(c[2]), "+f"(c[3])
        : "r"(a[0]), "r"(a[1]), "r"(a[2]), "r"(a[3]), "r"(b[0]), "r"(b[1]));
}

__device__ __forceinline__ void ldsm_x4(uint32_t* r, uint32_t addr) {
    asm volatile(
        "ldmatrix.sync.aligned.m8n8.x4.shared.b16 {%0,%1,%2,%3}, [%4];"
        : "=r"(r[0]), "=r"(r[1]), "=r"(r[2]), "=r"(r[3]) : "r"(addr));
}

// ---------------------------------------------------------------------------
// tf32 tensor-core GEMM body: C = A[M,K] @ B[K,N] + bias
// 128x128x16 CTA tile, 128 threads (4 warps, 2x2), warp tile 64x64.
// Double-buffered smem, one __syncthreads per k-tile.
// A fragments via ldmatrix.x4 ([m][k] smem, stride 20 words); B scalar [k][n].
// MODE 0: row-major [M,N].  MODE 1: QKV scatter to [B,H,T,D].
// ---------------------------------------------------------------------------
#define BM 128
#define BN 128
#define BK 16
#define ASTRIDE 20   // words per A row (16 k + 4 pad) -> LDSM conflict-free
#define LDSTB 136    // BN + 8 pad for B [k][n]

template <int MODE>
__device__ __forceinline__ void gemm_body(
    const float* __restrict__ A, const float* __restrict__ B,
    const float* __restrict__ bias, float* __restrict__ Cout,
    int M, int N, int K)
{
    __shared__ uint32_t SA[2][BM * ASTRIDE];   // [m][k] tf32
    __shared__ uint32_t SB[2][BK][LDSTB];      // [k][n] tf32

    const int tid  = threadIdx.x;      // 0..127
    const int bm   = blockIdx.y * BM;
    const int bn   = blockIdx.x * BN;
    const int wid  = tid >> 5;         // 0..3
    const int lane = tid & 31;
    const int g    = lane >> 2;
    const int tig  = lane & 3;
    const int wm   = (wid & 1) * 64;
    const int wn   = (wid >> 1) * 64;

    // Staging: A = 512 float4 chunks (128m x 4 kq), 4/thread; B likewise.
    const int a_m = tid >> 2;               const int a_k = (tid & 3) << 2;
    const int b_k = tid >> 5;               const int b_n = (tid & 31) << 2;

    const float* Ap[4];
    const float* Bp[4];
#pragma unroll
    for (int t = 0; t < 4; t++) {
        Ap[t] = A + (size_t)(bm + a_m + 32 * t) * K + a_k;
        Bp[t] = B + (size_t)(b_k + 4 * t) * N + bn + b_n;
    }

    float4 av[4], bv[4];
#pragma unroll
    for (int t = 0; t < 4; t++) {
        av[t] = *(const float4*)Ap[t];
        bv[t] = *(const float4*)Bp[t];
    }

    const uint32_t sa_base0 = (uint32_t)__cvta_generic_to_shared(&SA[0][0]);
    const uint32_t sa_base1 = (uint32_t)__cvta_generic_to_shared(&SA[1][0]);
    const uint32_t a_lane_off = (((lane & 15) * ASTRIDE) + ((lane >> 4) << 2)) * 4;

    float acc[4][8][4];
#pragma unroll
    for (int i = 0; i < 4; i++)
#pragma unroll
        for (int j = 0; j < 8; j++)
#pragma unroll
            for (int r = 0; r < 4; r++) acc[i][j][r] = 0.f;

#define STORE_TILE(bf)                                                        \
    do {                                                                      \
        _Pragma("unroll")                                                     \
        for (int t = 0; t < 4; t++) {                                         \
            *(uint4*)&SA[bf][(a_m + 32 * t) * ASTRIDE + a_k] =                \
                make_uint4(f2tf32(av[t].x), f2tf32(av[t].y),                  \
                           f2tf32(av[t].z), f2tf32(av[t].w));                 \
            *(uint4*)&SB[bf][b_k + 4 * t][b_n] =                              \
                make_uint4(f2tf32(bv[t].x), f2tf32(bv[t].y),                  \
                           f2tf32(bv[t].z), f2tf32(bv[t].w));                 \
        }                                                                     \
    } while (0)

    STORE_TILE(0);
    __syncthreads();

    int buf = 0;
    for (int k0 = 0; k0 < K; k0 += BK, buf ^= 1) {
        const bool has_next = (k0 + BK < K);
        if (has_next) {
#pragma unroll
            for (int t = 0; t < 4; t++) {
                Ap[t] += BK;
                Bp[t] += (size_t)BK * N;
                av[t] = *(const float4*)Ap[t];
                bv[t] = *(const float4*)Bp[t];
            }
        }

        const uint32_t sa_base = buf ? sa_base1 : sa_base0;
#pragma unroll
        for (int ks = 0; ks < BK; ks += 8) {
            uint32_t af[4][4], bfr[8][2];
#pragma unroll
            for (int i = 0; i < 4; i++) {
                const uint32_t addr =
                    sa_base + a_lane_off + (uint32_t)(((wm + 16 * i) * ASTRIDE + ks) * 4);
                ldsm_x4(af[i], addr);
            }
#pragma unroll
            for (int j = 0; j < 8; j++) {
                const int nb = wn + 8 * j;
                bfr[j][0] = SB[buf][ks + tig][nb + g];
                bfr[j][1] = SB[buf][ks + tig + 4][nb + g];
            }
#pragma unroll
            for (int i = 0; i < 4; i++)
#pragma unroll
                for (int j = 0; j < 8; j++)
                    mma_tf32(acc[i][j], af[i], bfr[j]);
        }

        if (has_next) STORE_TILE(buf ^ 1);
        __syncthreads();
    }
#undef STORE_TILE

#pragma unroll
    for (int j = 0; j < 8; j++) {
        const int col = bn + wn + 8 * j + 2 * tig;
        const float b0 = bias[col];
        const float b1 = bias[col + 1];
#pragma unroll
        for (int i = 0; i < 4; i++) {
            const int row = bm + wm + 16 * i + g;
            const float2 v0 = make_float2(acc[i][j][0] + b0, acc[i][j][1] + b1);
            const float2 v1 = make_float2(acc[i][j][2] + b0, acc[i][j][3] + b1);
            if (MODE == 0) {
                *(float2*)&Cout[(size_t)row * N + col] = v0;
                *(float2*)&Cout[(size_t)(row + 8) * N + col] = v1;
            } else {
                const int h_ = col >> 6;
                const int d_ = col & (HD - 1);
                const int b0_ = row >> 11;
                const int t0_ = row & (T_SEQ - 1);
                const int b1_ = (row + 8) >> 11;
                const int t1_ = (row + 8) & (T_SEQ - 1);
                *(float2*)&Cout[(((size_t)b0_ * NH + h_) * T_SEQ + t0_) * HD + d_] = v0;
                *(float2*)&Cout[(((size_t)b1_ * NH + h_) * T_SEQ + t1_) * HD + d_] = v1;
            }
        }
    }
}

// Fused QKV projection: blockIdx.z selects (W, bias, out). One tail wave.
__global__ __launch_bounds__(128) void gemm_qkv_tf32(
    const float* __restrict__ A,
    const float* __restrict__ W0, const float* __restrict__ W1, const float* __restrict__ W2,
    const float* __restrict__ c0, const float* __restrict__ c1, const float* __restrict__ c2,
    float* __restrict__ O0, float* __restrict__ O1, float* __restrict__ O2,
    int M, int N, int K)
{
    const int z = blockIdx.z;
    const float* B    = (z == 0) ? W0 : (z == 1) ? W1 : W2;
    const float* bias = (z == 0) ? c0 : (z == 1) ? c1 : c2;
    float* Cout       = (z == 0) ? O0 : (z == 1) ? O1 : O2;
    gemm_body<1>(A, B, bias, Cout, M, N, K);
}

__global__ __launch_bounds__(128) void gemm_out_tf32(
    const float* __restrict__ A, const float* __restrict__ B,
    const float* __restrict__ bias, float* __restrict__ Cout,
    int M, int N, int K)
{
    gemm_body<0>(A, B, bias, Cout, M, N, K);
}

// ---------------------------------------------------------------------------
// Tensor-core flash attention (tf32 mma, fp32 softmax/accum, causal).
// 128 queries/CTA, 64-key tiles, 8 warps x 16 query rows each.  (unchanged)
// ---------------------------------------------------------------------------
#define QS_STRIDE 68
#define KS_STRIDE 68
#define VS_STRIDE 72
#define ATTN_SMEM ((128 * QS_STRIDE + 64 * KS_STRIDE + 64 * VS_STRIDE) * 4)  // 70656 B

__global__ __launch_bounds__(256, 2) void attn_tc_kernel(
    const float* __restrict__ Q, const float* __restrict__ K,
    const float* __restrict__ V, float* __restrict__ Y)
{
    extern __shared__ uint32_t smu[];
    uint32_t* Qsm = smu;                          // [128][68] tf32 (pre-scaled)
    uint32_t* Ksm = smu + 128 * QS_STRIDE;        // [64][68]
    uint32_t* Vsm = Ksm + 64 * KS_STRIDE;         // [64][72]

    const int tid  = threadIdx.x;
    const int w    = tid >> 5;
    const int lane = tid & 31;
    const int g    = lane >> 2;
    const int tig  = lane & 3;
    const int bh   = blockIdx.y;
    const int qb   = blockIdx.x;
    const int q0   = qb * 128;

    const float* Qg = Q + ((size_t)bh * T_SEQ + q0) * HD;
    const float* Kg = K + (size_t)bh * T_SEQ * HD;
    const float* Vg = V + (size_t)bh * T_SEQ * HD;

#pragma unroll
    for (int r = 0; r < 8; r++) {
        const int idx = tid + r * 256;
        const int row = idx >> 4;
        const int d4  = (idx & 15) << 2;
        const float4 v = *(const float4*)(Qg + row * HD + d4);
        uint32_t* p = &Qsm[row * QS_STRIDE + d4];
        p[0] = f2tf32(v.x * 0.125f);
        p[1] = f2tf32(v.y * 0.125f);
        p[2] = f2tf32(v.z * 0.125f);
        p[3] = f2tf32(v.w * 0.125f);
    }

    float o[8][4];
#pragma unroll
    for (int j = 0; j < 8; j++)
#pragma unroll
        for (int r = 0; r < 4; r++) o[j][r] = 0.f;
    float m_lo = -1e30f, m_hi = -1e30f, l_lo = 0.f, l_hi = 0.f;

    const int r0      = 16 * w + g;
    const int row_lo  = q0 + r0;
    const int row_hi  = row_lo + 8;
    const int row_max_w = q0 + 16 * w + 15;
    const int qbase = lane & 28;
    const int srcA  = qbase + (tig >> 1);
    const int srcB  = srcA + 2;

    for (int s0 = 0; s0 < q0 + 128; s0 += 64) {
        __syncthreads();
#pragma unroll
        for (int r = 0; r < 4; r++) {
            const int idx = tid + r * 256;
            const int row = idx >> 4;
            const int d4  = (idx & 15) << 2;
            const float4 kv = *(const float4*)(Kg + (size_t)(s0 + row) * HD + d4);
            uint32_t* pk = &Ksm[row * KS_STRIDE + d4];
            pk[0] = f2tf32(kv.x); pk[1] = f2tf32(kv.y);
            pk[2] = f2tf32(kv.z); pk[3] = f2tf32(kv.w);
            const float4 vv = *(const float4*)(Vg + (size_t)(s0 + row) * HD + d4);
            uint32_t* pv = &Vsm[row * VS_STRIDE + d4];
            pv[0] = f2tf32(vv.x); pv[1] = f2tf32(vv.y);
            pv[2] = f2tf32(vv.z); pv[3] = f2tf32(vv.w);
        }
        __syncthreads();

        if (s0 > row_max_w) continue;

        float s_[8][4];
#pragma unroll
        for (int j = 0; j < 8; j++)
#pragma unroll
            for (int r = 0; r < 4; r++) s_[j][r] = 0.f;

#pragma unroll
        for (int ks = 0; ks < 8; ks++) {
            uint32_t a[4];
            a[0] = Qsm[r0 * QS_STRIDE + 8 * ks + tig];
            a[1] = Qsm[(r0 + 8) * QS_STRIDE + 8 * ks + tig];
            a[2] = Qsm[r0 * QS_STRIDE + 8 * ks + tig + 4];
            a[3] = Qsm[(r0 + 8) * QS_STRIDE + 8 * ks + tig + 4];
#pragma unroll
            for (int j = 0; j < 8; j++) {
                uint32_t b[2];
                b[0] = Ksm[(8 * j + g) * KS_STRIDE + 8 * ks + tig];
                b[1] = Ksm[(8 * j + g) * KS_STRIDE + 8 * ks + tig + 4];
                mma_tf32(s_[j], a, b);
            }
        }

        if (s0 + 63 > q0 + 16 * w) {
#pragma unroll
            for (int j = 0; j < 8; j++) {
                const int c0 = s0 + 8 * j + 2 * tig;
                if (c0 > row_lo)     s_[j][0] = -1e30f;
                if (c0 + 1 > row_lo) s_[j][1] = -1e30f;
                if (c0 > row_hi)     s_[j][2] = -1e30f;
                if (c0 + 1 > row_hi) s_[j][3] = -1e30f;
            }
        }

        float t_lo = -1e30f, t_hi = -1e30f;
#pragma unroll
        for (int j = 0; j < 8; j++) {
            t_lo = fmaxf(t_lo, fmaxf(s_[j][0], s_[j][1]));
            t_hi = fmaxf(t_hi, fmaxf(s_[j][2], s_[j][3]));
        }
        t_lo = fmaxf(t_lo, __shfl_xor_sync(0xffffffffu, t_lo, 1));
        t_lo = fmaxf(t_lo, __shfl_xor_sync(0xffffffffu, t_lo, 2));
        t_hi = fmaxf(t_hi, __shfl_xor_sync(0xffffffffu, t_hi, 1));
        t_hi = fmaxf(t_hi, __shfl_xor_sync(0xffffffffu, t_hi, 2));

        const float mn_lo = fmaxf(m_lo, t_lo);
        const float mn_hi = fmaxf(m_hi, t_hi);
        const float a_lo = __expf(m_lo - mn_lo);
        const float a_hi = __expf(m_hi - mn_hi);
        m_lo = mn_lo; m_hi = mn_hi;

        float rs_lo = 0.f, rs_hi = 0.f;
#pragma unroll
        for (int j = 0; j < 8; j++) {
            const float p0 = __expf(s_[j][0] - mn_lo);
            const float p1 = __expf(s_[j][1] - mn_lo);
            const float p2 = __expf(s_[j][2] - mn_hi);
            const float p3 = __expf(s_[j][3] - mn_hi);
            rs_lo += p0 + p1;
            rs_hi += p2 + p3;
            s_[j][0] = __uint_as_float(f2tf32(p0));
            s_[j][1] = __uint_as_float(f2tf32(p1));
            s_[j][2] = __uint_as_float(f2tf32(p2));
            s_[j][3] = __uint_as_float(f2tf32(p3));
        }
        rs_lo += __shfl_xor_sync(0xffffffffu, rs_lo, 1);
        rs_lo += __shfl_xor_sync(0xffffffffu, rs_lo, 2);
        rs_hi += __shfl_xor_sync(0xffffffffu, rs_hi, 1);
        rs_hi += __shfl_xor_sync(0xffffffffu, rs_hi, 2);
        l_lo = l_lo * a_lo + rs_lo;
        l_hi = l_hi * a_hi + rs_hi;

#pragma unroll
        for (int jd = 0; jd < 8; jd++) {
            o[jd][0] *= a_lo; o[jd][1] *= a_lo;
            o[jd][2] *= a_hi; o[jd][3] *= a_hi;
        }

#pragma unroll
        for (int ks = 0; ks < 8; ks++) {
            const float p0 = s_[ks][0], p1 = s_[ks][1];
            const float p2 = s_[ks][2], p3 = s_[ks][3];
            const float u0 = __shfl_sync(0xffffffffu, p0, srcA);
            const float u1 = __shfl_sync(0xffffffffu, p1, srcA);
            const float v0 = __shfl_sync(0xffffffffu, p2, srcA);
            const float v1 = __shfl_sync(0xffffffffu, p3, srcA);
            const float x0 = __shfl_sync(0xffffffffu, p0, srcB);
            const float x1 = __shfl_sync(0xffffffffu, p1, srcB);
            const float y0 = __shfl_sync(0xffffffffu, p2, srcB);
            const float y1 = __shfl_sync(0xffffffffu, p3, srcB);
            uint32_t a[4];
            a[0] = __float_as_uint((tig & 1) ? u1 : u0);
            a[1] = __float_as_uint((tig & 1) ? v1 : v0);
            a[2] = __float_as_uint((tig & 1) ? x1 : x0);
            a[3] = __float_as_uint((tig & 1) ? y1 : y0);
#pragma unroll
            for (int jd = 0; jd < 8; jd++) {
                uint32_t b[2];
                b[0] = Vsm[(8 * ks + tig) * VS_STRIDE + 8 * jd + g];
                b[1] = Vsm[(8 * ks + tig + 4) * VS_STRIDE + 8 * jd + g];
                mma_tf32(o[jd], a, b);
            }
        }
    }

    const float il_lo = 1.0f / l_lo;
    const float il_hi = 1.0f / l_hi;
    const int b_ = bh >> 4;
    const int h_ = bh & 15;
    float* Yb = Y + (size_t)b_ * T_SEQ * C_EMB + h_ * HD;
#pragma unroll
    for (int jd = 0; jd < 8; jd++) {
        const int d = 8 * jd + 2 * tig;
        const float2 vlo = make_float2(o[jd][0] * il_lo, o[jd][1] * il_lo);
        const float2 vhi = make_float2(o[jd][2] * il_hi, o[jd][3] * il_hi);
        *(float2*)&Yb[(size_t)row_lo * C_EMB + d] = vlo;
        *(float2*)&Yb[(size_t)row_hi * C_EMB + d] = vhi;
    }
}

// ---------------------------------------------------------------------------
extern "C" void kernel_launch(void* const* d_in, const int* in_sizes, int n_in,
                              void* d_out, int out_size)
{
    const float* x  = (const float*)d_in[0];
    const float* Wq = (const float*)d_in[1];
    const float* bq = (const float*)d_in[2];
    const float* Wk = (const float*)d_in[3];
    const float* bk = (const float*)d_in[4];
    const float* Wv = (const float*)d_in[5];
    const float* bv = (const float*)d_in[6];
    const float* Wp = (const float*)d_in[7];
    const float* bp = (const float*)d_in[8];
    float* out = (float*)d_out;

    float *Qp, *Kp, *Vp, *Yp;
    cudaGetSymbolAddress((void**)&Qp, g_Q);
    cudaGetSymbolAddress((void**)&Kp, g_K);
    cudaGetSymbolAddress((void**)&Vp, g_V);
    cudaGetSymbolAddress((void**)&Yp, g_Yatt);

    cudaFuncSetAttribute(attn_tc_kernel,
                         cudaFuncAttributeMaxDynamicSharedMemorySize, ATTN_SMEM);

    const dim3 gqkv(C_EMB / BN, M_ROWS / BM, 3);  // (8, 64, 3)
    gemm_qkv_tf32<<<gqkv, 128>>>(x, Wq, Wk, Wv, bq, bk, bv, Qp, Kp, Vp,
                                 M_ROWS, C_EMB, C_EMB);

    attn_tc_kernel<<<dim3(T_SEQ / 128, BATCH * NH), 256, ATTN_SMEM>>>(Qp, Kp, Vp, Yp);

    gemm_out_tf32<<<dim3(C_EMB / BN, M_ROWS / BM), 128>>>(Yp, Wp, bp, out,
                                                          M_ROWS, C_EMB, C_EMB);
}